// round 1
// baseline (speedup 1.0000x reference)
#include <cuda_runtime.h>
#include <math.h>

// ---------------------------------------------------------------------------
// Problem constants
// ---------------------------------------------------------------------------
#define Bsz   2
#define Ntok  2048
#define Dm    1024
#define Hh    16
#define DHd   64
#define Ii    1024
#define DCc   768
#define Mctx  77
#define FFd   4096
#define BN    (Bsz*Ntok)          // 4096
#define BM2   (Bsz*Mctx)          // 154
#define BHh   (Bsz*Hh)            // 32
#define SCALE 0.125f              // 64^-0.5

// ---------------------------------------------------------------------------
// Scratch (static device globals — allocation-free at launch time)
// ---------------------------------------------------------------------------
__device__ float g_ln   [(size_t)BN * Dm];
__device__ float g_q    [(size_t)BN * Ii];
__device__ float g_k    [(size_t)BN * Ii];
__device__ float g_v    [(size_t)BN * Ii];
__device__ float g_att  [(size_t)BN * Ii];
__device__ float g_x1   [(size_t)BN * Dm];
__device__ float g_x2   [(size_t)BN * Dm];
__device__ float g_sim  [(size_t)BHh * Ntok * Ntok];   // 512 MB, reused for sim2
__device__ float g_k2   [(size_t)BM2 * Ii];
__device__ float g_v2   [(size_t)BM2 * Ii];
__device__ float g_hg   [(size_t)BN * 2 * FFd];
__device__ float g_ffact[(size_t)BN * FFd];

// ---------------------------------------------------------------------------
// LayerNorm: one block per row of length D
// ---------------------------------------------------------------------------
__global__ __launch_bounds__(256) void layernorm_kernel(
    const float* __restrict__ x, const float* __restrict__ g,
    const float* __restrict__ b, float* __restrict__ out, int D)
{
    long row = blockIdx.x;
    const float* xr = x + row * (long)D;
    float* orow = out + row * (long)D;
    __shared__ float red[256];
    int t = threadIdx.x;

    float s = 0.f;
    for (int i = t; i < D; i += 256) s += xr[i];
    red[t] = s; __syncthreads();
    for (int o = 128; o > 0; o >>= 1) { if (t < o) red[t] += red[t + o]; __syncthreads(); }
    float mean = red[0] / (float)D;
    __syncthreads();

    float s2 = 0.f;
    for (int i = t; i < D; i += 256) { float d = xr[i] - mean; s2 += d * d; }
    red[t] = s2; __syncthreads();
    for (int o = 128; o > 0; o >>= 1) { if (t < o) red[t] += red[t + o]; __syncthreads(); }
    float inv = rsqrtf(red[0] / (float)D + 1e-5f);
    __syncthreads();

    for (int i = t; i < D; i += 256)
        orow[i] = (xr[i] - mean) * inv * g[i] + b[i];
}

// ---------------------------------------------------------------------------
// Row softmax: one block per row
// ---------------------------------------------------------------------------
__global__ __launch_bounds__(256) void softmax_kernel(float* __restrict__ s, int cols)
{
    long row = blockIdx.x;
    float* r = s + row * (long)cols;
    __shared__ float red[256];
    int t = threadIdx.x;

    float m = -INFINITY;
    for (int i = t; i < cols; i += 256) m = fmaxf(m, r[i]);
    red[t] = m; __syncthreads();
    for (int o = 128; o > 0; o >>= 1) { if (t < o) red[t] = fmaxf(red[t], red[t + o]); __syncthreads(); }
    m = red[0]; __syncthreads();

    float sum = 0.f;
    for (int i = t; i < cols; i += 256) { float e = __expf(r[i] - m); r[i] = e; sum += e; }
    red[t] = sum; __syncthreads();
    for (int o = 128; o > 0; o >>= 1) { if (t < o) red[t] += red[t + o]; __syncthreads(); }
    float inv = 1.f / red[0];
    __syncthreads();

    for (int i = t; i < cols; i += 256) r[i] *= inv;
}

// ---------------------------------------------------------------------------
// GEGLU: out[r,c] = hg[r,c] * gelu_exact(hg[r, FF + c])
// ---------------------------------------------------------------------------
__global__ __launch_bounds__(256) void geglu_kernel(
    const float* __restrict__ hg, float* __restrict__ out)
{
    long idx = (long)blockIdx.x * 256 + threadIdx.x;
    if (idx >= (long)BN * FFd) return;
    long r = idx / FFd; int c = (int)(idx % FFd);
    float h = hg[r * (2L * FFd) + c];
    float g = hg[r * (2L * FFd) + FFd + c];
    float gl = 0.5f * g * (1.f + erff(g * 0.70710678118654752440f));
    out[idx] = h * gl;
}

// ---------------------------------------------------------------------------
// Batched, boundary-guarded tiled SGEMM.
// C[m,n] = alpha * sum_k A[m,k] * B'[k,n]  (+bias[n]) (+resid[m,n])
// TRANSB=0: B' = B  (B stored [K,N], ldb)       (NN)
// TRANSB=1: B'[k,n] = B[n,k] (B stored [N,K])   (NT)
// Batch z: zo=z/nInner, zi=z%nInner; ptr += zo*s_o + zi*s_i.
// Tile 64x64, K-step 16, 256 threads, 4x4 per thread.
// ---------------------------------------------------------------------------
template<int TRANSB>
__global__ __launch_bounds__(256) void gemm_kernel(
    const float* __restrict__ A, const float* __restrict__ B,
    const float* __restrict__ bias, const float* __restrict__ resid,
    float* __restrict__ C,
    int M, int N, int K, int lda, int ldb, int ldc,
    long long sA_o, long long sA_i, long long sB_o, long long sB_i,
    long long sC_o, long long sC_i, int nInner, float alpha)
{
    int z = blockIdx.z;
    int zo = z / nInner, zi = z % nInner;
    A += zo * sA_o + zi * sA_i;
    B += zo * sB_o + zi * sB_i;
    C += zo * sC_o + zi * sC_i;

    __shared__ float As[64][17];   // [m][k]
    __shared__ float Bs[16][65];   // [k][n]

    int tid = threadIdx.x;
    int tx = tid & 15, ty = tid >> 4;
    int rowBase = blockIdx.y * 64;
    int colBase = blockIdx.x * 64;

    float acc[4][4] = {};

    for (int k0 = 0; k0 < K; k0 += 16) {
        // A tile 64x16
        {
            int r  = tid >> 2;
            int kk = (tid & 3) << 2;
            int grow = rowBase + r;
            #pragma unroll
            for (int i = 0; i < 4; i++) {
                int gk = k0 + kk + i;
                As[r][kk + i] = (grow < M && gk < K) ? A[(long)grow * lda + gk] : 0.f;
            }
        }
        // B tile 16x64
        if (TRANSB == 0) {
            int kr = tid >> 4;
            int c  = (tid & 15) << 2;
            int gk = k0 + kr;
            #pragma unroll
            for (int j = 0; j < 4; j++) {
                int gc = colBase + c + j;
                Bs[kr][c + j] = (gk < K && gc < N) ? B[(long)gk * ldb + gc] : 0.f;
            }
        } else {
            int c  = tid >> 2;
            int kk = (tid & 3) << 2;
            int gc = colBase + c;
            #pragma unroll
            for (int i = 0; i < 4; i++) {
                int gk = k0 + kk + i;
                Bs[kk + i][c] = (gc < N && gk < K) ? B[(long)gc * ldb + gk] : 0.f;
            }
        }
        __syncthreads();

        #pragma unroll
        for (int k = 0; k < 16; k++) {
            float a[4], bb[4];
            #pragma unroll
            for (int i = 0; i < 4; i++) a[i] = As[ty * 4 + i][k];
            #pragma unroll
            for (int j = 0; j < 4; j++) bb[j] = Bs[k][tx * 4 + j];
            #pragma unroll
            for (int i = 0; i < 4; i++)
                #pragma unroll
                for (int j = 0; j < 4; j++)
                    acc[i][j] += a[i] * bb[j];
        }
        __syncthreads();
    }

    #pragma unroll
    for (int i = 0; i < 4; i++) {
        int gr = rowBase + ty * 4 + i;
        if (gr >= M) continue;
        #pragma unroll
        for (int j = 0; j < 4; j++) {
            int gc = colBase + tx * 4 + j;
            if (gc >= N) continue;
            float v = acc[i][j] * alpha;
            if (bias)  v += bias[gc];
            if (resid) v += resid[(long)gr * ldc + gc];
            C[(long)gr * ldc + gc] = v;
        }
    }
}

// ---------------------------------------------------------------------------
// Launch orchestration
// ---------------------------------------------------------------------------
static inline dim3 gemm_grid(int M, int N, int batch) {
    return dim3((N + 63) / 64, (M + 63) / 64, batch);
}

extern "C" void kernel_launch(void* const* d_in, const int* in_sizes, int n_in,
                              void* d_out, int out_size)
{
    const float* x     = (const float*)d_in[0];
    const float* ctx   = (const float*)d_in[1];
    const float* ln1_g = (const float*)d_in[2];
    const float* ln1_b = (const float*)d_in[3];
    const float* ln2_g = (const float*)d_in[4];
    const float* ln2_b = (const float*)d_in[5];
    const float* ln3_g = (const float*)d_in[6];
    const float* ln3_b = (const float*)d_in[7];
    const float* Wq1   = (const float*)d_in[8];
    const float* Wk1   = (const float*)d_in[9];
    const float* Wv1   = (const float*)d_in[10];
    const float* Wo1   = (const float*)d_in[11];
    const float* bo1   = (const float*)d_in[12];
    const float* Wq2   = (const float*)d_in[13];
    const float* Wk2   = (const float*)d_in[14];
    const float* Wv2   = (const float*)d_in[15];
    const float* Wo2   = (const float*)d_in[16];
    const float* bo2   = (const float*)d_in[17];
    const float* Wff1  = (const float*)d_in[18];
    const float* bff1  = (const float*)d_in[19];
    const float* Wff2  = (const float*)d_in[20];
    const float* bff2  = (const float*)d_in[21];
    float* out = (float*)d_out;

    float *ln, *q, *k, *v, *att, *x1, *x2, *sim, *k2, *v2, *hg, *ffact;
    cudaGetSymbolAddress((void**)&ln,    g_ln);
    cudaGetSymbolAddress((void**)&q,     g_q);
    cudaGetSymbolAddress((void**)&k,     g_k);
    cudaGetSymbolAddress((void**)&v,     g_v);
    cudaGetSymbolAddress((void**)&att,   g_att);
    cudaGetSymbolAddress((void**)&x1,    g_x1);
    cudaGetSymbolAddress((void**)&x2,    g_x2);
    cudaGetSymbolAddress((void**)&sim,   g_sim);
    cudaGetSymbolAddress((void**)&k2,    g_k2);
    cudaGetSymbolAddress((void**)&v2,    g_v2);
    cudaGetSymbolAddress((void**)&hg,    g_hg);
    cudaGetSymbolAddress((void**)&ffact, g_ffact);

    // ---- block 1: self-attention --------------------------------------
    layernorm_kernel<<<BN, 256>>>(x, ln1_g, ln1_b, ln, Dm);

    gemm_kernel<0><<<gemm_grid(BN, Ii, 1), 256>>>(ln, Wq1, nullptr, nullptr, q,
        BN, Ii, Dm, Dm, Ii, Ii, 0, 0, 0, 0, 0, 0, 1, 1.f);
    gemm_kernel<0><<<gemm_grid(BN, Ii, 1), 256>>>(ln, Wk1, nullptr, nullptr, k,
        BN, Ii, Dm, Dm, Ii, Ii, 0, 0, 0, 0, 0, 0, 1, 1.f);
    gemm_kernel<0><<<gemm_grid(BN, Ii, 1), 256>>>(ln, Wv1, nullptr, nullptr, v,
        BN, Ii, Dm, Dm, Ii, Ii, 0, 0, 0, 0, 0, 0, 1, 1.f);

    // sim[b,h] = q(Nx64) @ k(Nx64)^T * SCALE
    gemm_kernel<1><<<gemm_grid(Ntok, Ntok, BHh), 256>>>(q, k, nullptr, nullptr, sim,
        Ntok, Ntok, DHd, Ii, Ii, Ntok,
        (long long)Ntok * Ii, 64,
        (long long)Ntok * Ii, 64,
        (long long)Hh * Ntok * Ntok, (long long)Ntok * Ntok,
        Hh, SCALE);

    softmax_kernel<<<BHh * Ntok, 256>>>(sim, Ntok);

    // att[b,h] = sim(NxN) @ v(Nx64)
    gemm_kernel<0><<<gemm_grid(Ntok, DHd, BHh), 256>>>(sim, v, nullptr, nullptr, att,
        Ntok, DHd, Ntok, Ntok, Ii, Ii,
        (long long)Hh * Ntok * Ntok, (long long)Ntok * Ntok,
        (long long)Ntok * Ii, 64,
        (long long)Ntok * Ii, 64,
        Hh, 1.f);

    // x1 = att @ Wo1 + bo1 + x
    gemm_kernel<0><<<gemm_grid(BN, Dm, 1), 256>>>(att, Wo1, bo1, x, x1,
        BN, Dm, Ii, Ii, Dm, Dm, 0, 0, 0, 0, 0, 0, 1, 1.f);

    // ---- block 2: cross-attention --------------------------------------
    layernorm_kernel<<<BN, 256>>>(x1, ln2_g, ln2_b, ln, Dm);

    gemm_kernel<0><<<gemm_grid(BN, Ii, 1), 256>>>(ln, Wq2, nullptr, nullptr, q,
        BN, Ii, Dm, Dm, Ii, Ii, 0, 0, 0, 0, 0, 0, 1, 1.f);
    gemm_kernel<0><<<gemm_grid(BM2, Ii, 1), 256>>>(ctx, Wk2, nullptr, nullptr, k2,
        BM2, Ii, DCc, DCc, Ii, Ii, 0, 0, 0, 0, 0, 0, 1, 1.f);
    gemm_kernel<0><<<gemm_grid(BM2, Ii, 1), 256>>>(ctx, Wv2, nullptr, nullptr, v2,
        BM2, Ii, DCc, DCc, Ii, Ii, 0, 0, 0, 0, 0, 0, 1, 1.f);

    // sim2[b,h] = q(Nx64) @ k2(77x64)^T * SCALE
    gemm_kernel<1><<<gemm_grid(Ntok, Mctx, BHh), 256>>>(q, k2, nullptr, nullptr, sim,
        Ntok, Mctx, DHd, Ii, Ii, Mctx,
        (long long)Ntok * Ii, 64,
        (long long)Mctx * Ii, 64,
        (long long)Hh * Ntok * Mctx, (long long)Ntok * Mctx,
        Hh, SCALE);

    softmax_kernel<<<BHh * Ntok, 256>>>(sim, Mctx);

    // att[b,h] = sim2(Nx77) @ v2(77x64)
    gemm_kernel<0><<<gemm_grid(Ntok, DHd, BHh), 256>>>(sim, v2, nullptr, nullptr, att,
        Ntok, DHd, Mctx, Mctx, Ii, Ii,
        (long long)Hh * Ntok * Mctx, (long long)Ntok * Mctx,
        (long long)Mctx * Ii, 64,
        (long long)Ntok * Ii, 64,
        Hh, 1.f);

    // x2 = att @ Wo2 + bo2 + x1
    gemm_kernel<0><<<gemm_grid(BN, Dm, 1), 256>>>(att, Wo2, bo2, x1, x2,
        BN, Dm, Ii, Ii, Dm, Dm, 0, 0, 0, 0, 0, 0, 1, 1.f);

    // ---- block 3: GEGLU feed-forward ------------------------------------
    layernorm_kernel<<<BN, 256>>>(x2, ln3_g, ln3_b, ln, Dm);

    gemm_kernel<0><<<gemm_grid(BN, 2 * FFd, 1), 256>>>(ln, Wff1, bff1, nullptr, hg,
        BN, 2 * FFd, Dm, Dm, 2 * FFd, 2 * FFd, 0, 0, 0, 0, 0, 0, 1, 1.f);

    geglu_kernel<<<(int)(((long)BN * FFd + 255) / 256), 256>>>(hg, ffact);

    // out = ffact @ Wff2 + bff2 + x2
    gemm_kernel<0><<<gemm_grid(BN, Dm, 1), 256>>>(ffact, Wff2, bff2, x2, out,
        BN, Dm, FFd, FFd, Dm, Dm, 0, 0, 0, 0, 0, 0, 1, 1.f);
}

// round 3
// speedup vs baseline: 3.1127x; 3.1127x over previous
#include <cuda_runtime.h>
#include <cuda_fp16.h>
#include <math.h>
#include <stdint.h>

// ---------------------------------------------------------------------------
// Problem constants
// ---------------------------------------------------------------------------
#define Bsz   2
#define Ntok  2048
#define Dm    1024
#define Hh    16
#define DHd   64
#define Ii    1024
#define DCc   768
#define Mctx  77
#define MctxP 80            // padded to multiple of 8
#define FFd   4096
#define BN    (Bsz*Ntok)    // 4096
#define BM2   (Bsz*Mctx)    // 154
#define BHh   (Bsz*Hh)      // 32
#define SCALE 0.125f

// ---------------------------------------------------------------------------
// Device scratch (allocation-free)
// ---------------------------------------------------------------------------
#define DEVARR(name, type, count) __device__ __align__(16) type name[(size_t)(count)]

DEVARR(g_lnh,  half, BN*Dm);   DEVARR(g_lnl,  half, BN*Dm);
DEVARR(g_qh,   half, BN*Ii);   DEVARR(g_ql,   half, BN*Ii);
DEVARR(g_kh,   half, BN*Ii);   DEVARR(g_kl,   half, BN*Ii);
DEVARR(g_v,    float, BN*Ii);
DEVARR(g_vth,  half, BHh*DHd*Ntok); DEVARR(g_vtl, half, BHh*DHd*Ntok);
DEVARR(g_sim,  float, (size_t)BHh*Ntok*Ntok);
DEVARR(g_Ph,   half, (size_t)BHh*Ntok*Ntok); DEVARR(g_Pl, half, (size_t)BHh*Ntok*Ntok);
DEVARR(g_atth, half, BN*Ii);   DEVARR(g_attl, half, BN*Ii);
DEVARR(g_x1,   float, BN*Dm);  DEVARR(g_x2,   float, BN*Dm);
DEVARR(g_ctxh, half, BM2*DCc); DEVARR(g_ctxl, half, BM2*DCc);
DEVARR(g_hg,   float, (size_t)BN*2*FFd);
DEVARR(g_ffh,  half, (size_t)BN*FFd); DEVARR(g_ffl, half, (size_t)BN*FFd);
// transposed/split weights [N x K]
DEVARR(g_wq1h, half, Dm*Ii);  DEVARR(g_wq1l, half, Dm*Ii);
DEVARR(g_wk1h, half, Dm*Ii);  DEVARR(g_wk1l, half, Dm*Ii);
DEVARR(g_wv1h, half, Dm*Ii);  DEVARR(g_wv1l, half, Dm*Ii);
DEVARR(g_wo1h, half, Dm*Ii);  DEVARR(g_wo1l, half, Dm*Ii);
DEVARR(g_wq2h, half, Dm*Ii);  DEVARR(g_wq2l, half, Dm*Ii);
DEVARR(g_wk2h, half, DCc*Ii); DEVARR(g_wk2l, half, DCc*Ii);
DEVARR(g_wv2h, half, DCc*Ii); DEVARR(g_wv2l, half, DCc*Ii);
DEVARR(g_wo2h, half, Dm*Ii);  DEVARR(g_wo2l, half, Dm*Ii);
DEVARR(g_wf1h, half, (size_t)Dm*2*FFd); DEVARR(g_wf1l, half, (size_t)Dm*2*FFd);
DEVARR(g_wf2h, half, (size_t)FFd*Dm);   DEVARR(g_wf2l, half, (size_t)FFd*Dm);

// ---------------------------------------------------------------------------
// Helpers
// ---------------------------------------------------------------------------
__device__ __forceinline__ uint32_t smem_u32(const void* p) {
    uint32_t a;
    asm("{ .reg .u64 t; cvta.to.shared.u64 t, %1; cvt.u32.u64 %0, t; }" : "=r"(a) : "l"(p));
    return a;
}
__device__ __forceinline__ void split2(float x, half& h, half& l) {
    h = __float2half_rn(x);
    l = __float2half_rn(x - __half2float(h));
}

#define LDSM4(r0, r1, r2, r3, addr) \
    asm volatile("ldmatrix.sync.aligned.m8n8.x4.shared.b16 {%0,%1,%2,%3}, [%4];" \
        : "=r"(r0), "=r"(r1), "=r"(r2), "=r"(r3) : "r"(addr))

#define MMA16816(c, a, b0, b1) \
    asm volatile("mma.sync.aligned.m16n8k16.row.col.f32.f16.f16.f32 " \
        "{%0,%1,%2,%3}, {%4,%5,%6,%7}, {%8,%9}, {%0,%1,%2,%3};" \
        : "+f"((c)[0]), "+f"((c)[1]), "+f"((c)[2]), "+f"((c)[3]) \
        : "r"((a)[0]), "r"((a)[1]), "r"((a)[2]), "r"((a)[3]), "r"(b0), "r"(b1))

// ---------------------------------------------------------------------------
// mma.sync fp16-split GEMM: C = alpha * A @ B^T (+bias)(+resid)
// A split [M x K] (lda), B split [N x K] (ldb). 3 passes: AhBh + AhBl + AlBh.
// Block tile 128x128, BK=32, 8 warps (warp tile 32x64), cp.async double buffer.
// ---------------------------------------------------------------------------
#define PITCH   40                    // halves per SMEM row (32 + 8 pad)
#define TILE_H  (128*PITCH)           // halves per tile
#define STAGE_H (4*TILE_H)            // Ah, Al, Bh, Bl
#define SMEM_BYTES (2*STAGE_H*2)      // 81920 B

__global__ void __launch_bounds__(256) mma_gemm(
    const half* __restrict__ Ah_, const half* __restrict__ Al_,
    const half* __restrict__ Bh_, const half* __restrict__ Bl_,
    const float* __restrict__ bias, const float* __restrict__ resid,
    float* __restrict__ C, half* __restrict__ Ch, half* __restrict__ Cl,
    int M, int N, int K, int lda, int ldb, int ldc,
    long long aO, long long aI, long long bO, long long bI,
    long long cO, long long cI, int nInner, float alpha)
{
    extern __shared__ half sm[];
    uint32_t smBase = smem_u32(sm);
    int tid = threadIdx.x, lane = tid & 31, wid = tid >> 5;
    int warpM = wid >> 1, warpN = wid & 1;

    int z = blockIdx.z, zo = z / nInner, zi = z % nInner;
    const half* Ahp = Ah_ + (long long)zo * aO + (long long)zi * aI;
    const half* Alp = Al_ + (long long)zo * aO + (long long)zi * aI;
    const half* Bhp = Bh_ + (long long)zo * bO + (long long)zi * bI;
    const half* Blp = Bl_ + (long long)zo * bO + (long long)zi * bI;
    long long offC = (long long)zo * cO + (long long)zi * cI;

    int rowBase = blockIdx.y * 128, colBase = blockIdx.x * 128;

    float acc[2][8][4];
    #pragma unroll
    for (int i = 0; i < 2; i++)
        #pragma unroll
        for (int j = 0; j < 8; j++)
            #pragma unroll
            for (int e = 0; e < 4; e++) acc[i][j][e] = 0.f;

    int nc = (K + 31) >> 5;

    // ---- stage loader: 2048 x 16B cp.async per stage ----
    auto load_stage = [&](int c, int s) {
        int k0 = c << 5;
        #pragma unroll
        for (int i = 0; i < 8; i++) {
            int seg  = tid + (i << 8);          // 0..2047
            int tile = seg >> 9;                // 0:Ah 1:Al 2:Bh 3:Bl
            int w    = seg & 511;
            int row  = w >> 2;
            int cs   = (w & 3) << 3;            // half col within BK
            bool isA = tile < 2;
            const half* base = (tile == 0) ? Ahp : (tile == 1) ? Alp
                             : (tile == 2) ? Bhp : Blp;
            int ld  = isA ? lda : ldb;
            int gr  = (isA ? rowBase : colBase) + row;
            int gk  = k0 + cs;
            bool ok = (gr < (isA ? M : N)) && (gk + 8 <= K);
            const half* src = ok ? (base + (size_t)gr * ld + gk) : base;
            uint32_t dst = smBase + (uint32_t)(((s * 4 + tile) * TILE_H + row * PITCH + cs) * 2);
            uint32_t sz = ok ? 16u : 0u;
            asm volatile("cp.async.cg.shared.global [%0], [%1], 16, %2;"
                         :: "r"(dst), "l"(src), "r"(sz) : "memory");
        }
    };

    // ---- compute one stage (BK=32 -> 2 k16 steps) ----
    int aRow = (lane & 7) + ((lane >> 3) & 1) * 8;
    int aCg  = (lane >> 4) * 8;
    int bRow = (lane & 7) + (lane >> 4) * 8;
    int bCg  = ((lane >> 3) & 1) * 8;

    auto compute_stage = [&](int s) {
        uint32_t sBase = smBase + (uint32_t)(s * STAGE_H * 2);
        #pragma unroll
        for (int ks = 0; ks < 2; ks++) {
            uint32_t ah[2][4], al[2][4];
            #pragma unroll
            for (int mm = 0; mm < 2; mm++) {
                uint32_t addr = sBase + (uint32_t)(((warpM * 32 + mm * 16 + aRow) * PITCH + ks * 16 + aCg) * 2);
                LDSM4(ah[mm][0], ah[mm][1], ah[mm][2], ah[mm][3], addr);
                LDSM4(al[mm][0], al[mm][1], al[mm][2], al[mm][3], addr + TILE_H * 2);
            }
            #pragma unroll
            for (int nn = 0; nn < 4; nn++) {
                uint32_t baddr = sBase + (uint32_t)((2 * TILE_H + (warpN * 64 + nn * 16 + bRow) * PITCH + ks * 16 + bCg) * 2);
                uint32_t bh[4], bl[4];
                LDSM4(bh[0], bh[1], bh[2], bh[3], baddr);
                LDSM4(bl[0], bl[1], bl[2], bl[3], baddr + TILE_H * 2);
                #pragma unroll
                for (int mm = 0; mm < 2; mm++) {
                    MMA16816(acc[mm][2 * nn],     ah[mm], bh[0], bh[1]);
                    MMA16816(acc[mm][2 * nn + 1], ah[mm], bh[2], bh[3]);
                    MMA16816(acc[mm][2 * nn],     ah[mm], bl[0], bl[1]);
                    MMA16816(acc[mm][2 * nn + 1], ah[mm], bl[2], bl[3]);
                    MMA16816(acc[mm][2 * nn],     al[mm], bh[0], bh[1]);
                    MMA16816(acc[mm][2 * nn + 1], al[mm], bh[2], bh[3]);
                }
            }
        }
    };

    // ---- pipelined main loop ----
    load_stage(0, 0);
    asm volatile("cp.async.commit_group;" ::: "memory");
    for (int c = 0; c < nc; c++) {
        if (c + 1 < nc) load_stage(c + 1, (c + 1) & 1);
        asm volatile("cp.async.commit_group;" ::: "memory");
        asm volatile("cp.async.wait_group 1;" ::: "memory");
        __syncthreads();
        compute_stage(c & 1);
        __syncthreads();
    }

    // ---- epilogue ----
    #pragma unroll
    for (int mm = 0; mm < 2; mm++) {
        #pragma unroll
        for (int nf = 0; nf < 8; nf++) {
            int r  = rowBase + warpM * 32 + mm * 16 + (lane >> 2);
            int cc = colBase + warpN * 64 + nf * 8 + (lane & 3) * 2;
            #pragma unroll
            for (int e = 0; e < 4; e++) {
                int rr = r + (e >> 1) * 8;
                int gc = cc + (e & 1);
                if (rr < M && gc < N) {
                    float v = acc[mm][nf][e] * alpha;
                    if (bias) v += bias[gc];
                    size_t idx = (size_t)offC + (size_t)rr * ldc + gc;
                    if (resid) v += resid[idx];
                    if (C) C[idx] = v;
                    if (Ch) { half h, l; split2(v, h, l); Ch[idx] = h; Cl[idx] = l; }
                }
            }
        }
    }
}

// ---------------------------------------------------------------------------
// LayerNorm -> split fp16
// ---------------------------------------------------------------------------
__global__ __launch_bounds__(256) void ln_split_kernel(
    const float* __restrict__ x, const float* __restrict__ g, const float* __restrict__ b,
    half* __restrict__ oh, half* __restrict__ ol)
{
    size_t row = blockIdx.x;
    const float* xr = x + row * Dm;
    __shared__ float red[256];
    int t = threadIdx.x;
    float v[4];
    float s = 0.f;
    #pragma unroll
    for (int j = 0; j < 4; j++) { v[j] = xr[t + j * 256]; s += v[j]; }
    red[t] = s; __syncthreads();
    for (int o = 128; o > 0; o >>= 1) { if (t < o) red[t] += red[t + o]; __syncthreads(); }
    float mean = red[0] * (1.f / Dm);
    __syncthreads();
    float s2 = 0.f;
    #pragma unroll
    for (int j = 0; j < 4; j++) { float d = v[j] - mean; s2 += d * d; }
    red[t] = s2; __syncthreads();
    for (int o = 128; o > 0; o >>= 1) { if (t < o) red[t] += red[t + o]; __syncthreads(); }
    float inv = rsqrtf(red[0] * (1.f / Dm) + 1e-5f);
    #pragma unroll
    for (int j = 0; j < 4; j++) {
        int i = t + j * 256;
        float val = (v[j] - mean) * inv * g[i] + b[i];
        half h, l; split2(val, h, l);
        oh[row * Dm + i] = h; ol[row * Dm + i] = l;
    }
}

// ---------------------------------------------------------------------------
// Softmax -> split fp16 (zero-padded to ldout)
// ---------------------------------------------------------------------------
template<int VPT>
__global__ __launch_bounds__(256) void softmax_split_kernel(
    const float* __restrict__ s, half* __restrict__ ph, half* __restrict__ pl,
    int cols, int ldin, int ldout)
{
    size_t row = blockIdx.x;
    const float* r = s + row * (size_t)ldin;
    __shared__ float red[256];
    int t = threadIdx.x;
    float v[VPT];
    float m = -INFINITY;
    #pragma unroll
    for (int j = 0; j < VPT; j++) {
        int i = t + j * 256;
        v[j] = (i < cols) ? r[i] : -INFINITY;
        m = fmaxf(m, v[j]);
    }
    red[t] = m; __syncthreads();
    for (int o = 128; o > 0; o >>= 1) { if (t < o) red[t] = fmaxf(red[t], red[t + o]); __syncthreads(); }
    m = red[0]; __syncthreads();
    float sum = 0.f;
    #pragma unroll
    for (int j = 0; j < VPT; j++) {
        int i = t + j * 256;
        v[j] = (i < cols) ? __expf(v[j] - m) : 0.f;
        sum += v[j];
    }
    red[t] = sum; __syncthreads();
    for (int o = 128; o > 0; o >>= 1) { if (t < o) red[t] += red[t + o]; __syncthreads(); }
    float inv = 1.f / red[0];
    #pragma unroll
    for (int j = 0; j < VPT; j++) {
        int i = t + j * 256;
        if (i < ldout) {
            half h, l; split2(v[j] * inv, h, l);
            ph[row * (size_t)ldout + i] = h;
            pl[row * (size_t)ldout + i] = l;
        }
    }
}

// ---------------------------------------------------------------------------
// GEGLU -> split fp16
// ---------------------------------------------------------------------------
__global__ __launch_bounds__(256) void geglu_split_kernel(
    const float* __restrict__ hg, half* __restrict__ oh, half* __restrict__ ol)
{
    size_t idx = (size_t)blockIdx.x * 256 + threadIdx.x;
    if (idx >= (size_t)BN * FFd) return;
    size_t r = idx / FFd; int c = (int)(idx % FFd);
    float h = hg[r * (2 * FFd) + c];
    float g = hg[r * (2 * FFd) + FFd + c];
    float gl = 0.5f * g * (1.f + erff(g * 0.70710678118654752440f));
    half hh, ll; split2(h * gl, hh, ll);
    oh[idx] = hh; ol[idx] = ll;
}

// ---------------------------------------------------------------------------
// Plain split (elementwise)
// ---------------------------------------------------------------------------
__global__ __launch_bounds__(256) void split_kernel(
    const float* __restrict__ src, half* __restrict__ dh, half* __restrict__ dl, long long n)
{
    long long i = (long long)blockIdx.x * 256 + threadIdx.x;
    if (i >= n) return;
    half h, l; split2(src[i], h, l);
    dh[i] = h; dl[i] = l;
}

// ---------------------------------------------------------------------------
// Transpose + split: src [R x C] fp32 -> dst [C x R] fp16 hi/lo
// ---------------------------------------------------------------------------
__global__ __launch_bounds__(1024) void tsplit_kernel(
    const float* __restrict__ src, half* __restrict__ dh, half* __restrict__ dl, int R, int C)
{
    __shared__ float tile[32][33];
    int c0 = blockIdx.x * 32, r0 = blockIdx.y * 32;
    int tx = threadIdx.x, ty = threadIdx.y;
    int r = r0 + ty, c = c0 + tx;
    tile[ty][tx] = (r < R && c < C) ? src[(size_t)r * C + c] : 0.f;
    __syncthreads();
    int rr = r0 + tx, cc = c0 + ty;
    if (rr < R && cc < C) {
        half h, l; split2(tile[tx][ty], h, l);
        dh[(size_t)cc * R + rr] = h;
        dl[(size_t)cc * R + rr] = l;
    }
}

// ---------------------------------------------------------------------------
// Per-head transpose+split: v [(b*T + t)*1024 + h*64 + d] fp32
//   -> dst [(b*16+h)*64*Tpad + d*Tpad + t] fp16 hi/lo, zeros for t in [T,Tpad)
// ---------------------------------------------------------------------------
__global__ __launch_bounds__(1024) void head_tsplit_kernel(
    const float* __restrict__ src, half* __restrict__ dh, half* __restrict__ dl,
    int T, int Tpad)
{
    __shared__ float tile[32][33];
    int zh = blockIdx.z;               // b*16 + h
    int b = zh >> 4, h = zh & 15;
    int tx = threadIdx.x, ty = threadIdx.y;
    int t0 = blockIdx.x * 32, d0 = blockIdx.y * 32;
    int t = t0 + ty, d = d0 + tx;
    tile[ty][tx] = (t < T) ? src[((size_t)b * T + t) * 1024 + h * 64 + d] : 0.f;
    __syncthreads();
    int dd = d0 + ty, tt = t0 + tx;
    if (tt < Tpad) {
        half hh, ll; split2(tile[tx][ty], hh, ll);
        size_t base = (size_t)zh * 64 * Tpad + (size_t)dd * Tpad + tt;
        dh[base] = hh; dl[base] = ll;
    }
}

// ---------------------------------------------------------------------------
// Orchestration
// ---------------------------------------------------------------------------
static inline dim3 ggrid(int M, int N, int z) { return dim3((N + 127) / 128, (M + 127) / 128, z); }

#define SYM(p, s) cudaGetSymbolAddress((void**)&p, s)

extern "C" void kernel_launch(void* const* d_in, const int* in_sizes, int n_in,
                              void* d_out, int out_size)
{
    const float* x     = (const float*)d_in[0];
    const float* ctx   = (const float*)d_in[1];
    const float* ln1_g = (const float*)d_in[2];
    const float* ln1_b = (const float*)d_in[3];
    const float* ln2_g = (const float*)d_in[4];
    const float* ln2_b = (const float*)d_in[5];
    const float* ln3_g = (const float*)d_in[6];
    const float* ln3_b = (const float*)d_in[7];
    const float* Wq1   = (const float*)d_in[8];
    const float* Wk1   = (const float*)d_in[9];
    const float* Wv1   = (const float*)d_in[10];
    const float* Wo1   = (const float*)d_in[11];
    const float* bo1   = (const float*)d_in[12];
    const float* Wq2   = (const float*)d_in[13];
    const float* Wk2   = (const float*)d_in[14];
    const float* Wv2   = (const float*)d_in[15];
    const float* Wo2   = (const float*)d_in[16];
    const float* bo2   = (const float*)d_in[17];
    const float* Wff1  = (const float*)d_in[18];
    const float* bff1  = (const float*)d_in[19];
    const float* Wff2  = (const float*)d_in[20];
    const float* bff2  = (const float*)d_in[21];
    float* out = (float*)d_out;

    half *lnh,*lnl,*qh,*ql,*kh,*kl,*vth,*vtl,*Ph,*Pl,*atth,*attl,*ctxh,*ctxl,*ffh,*ffl;
    half *wq1h,*wq1l,*wk1h,*wk1l,*wv1h,*wv1l,*wo1h,*wo1l;
    half *wq2h,*wq2l,*wk2h,*wk2l,*wv2h,*wv2l,*wo2h,*wo2l,*wf1h,*wf1l,*wf2h,*wf2l;
    float *v,*sim,*x1,*x2,*hg;
    SYM(lnh,g_lnh); SYM(lnl,g_lnl); SYM(qh,g_qh); SYM(ql,g_ql); SYM(kh,g_kh); SYM(kl,g_kl);
    SYM(v,g_v); SYM(vth,g_vth); SYM(vtl,g_vtl); SYM(sim,g_sim); SYM(Ph,g_Ph); SYM(Pl,g_Pl);
    SYM(atth,g_atth); SYM(attl,g_attl); SYM(x1,g_x1); SYM(x2,g_x2);
    SYM(ctxh,g_ctxh); SYM(ctxl,g_ctxl); SYM(hg,g_hg); SYM(ffh,g_ffh); SYM(ffl,g_ffl);
    SYM(wq1h,g_wq1h); SYM(wq1l,g_wq1l); SYM(wk1h,g_wk1h); SYM(wk1l,g_wk1l);
    SYM(wv1h,g_wv1h); SYM(wv1l,g_wv1l); SYM(wo1h,g_wo1h); SYM(wo1l,g_wo1l);
    SYM(wq2h,g_wq2h); SYM(wq2l,g_wq2l); SYM(wk2h,g_wk2h); SYM(wk2l,g_wk2l);
    SYM(wv2h,g_wv2h); SYM(wv2l,g_wv2l); SYM(wo2h,g_wo2h); SYM(wo2l,g_wo2l);
    SYM(wf1h,g_wf1h); SYM(wf1l,g_wf1l); SYM(wf2h,g_wf2h); SYM(wf2l,g_wf2l);

    cudaFuncSetAttribute(mma_gemm, cudaFuncAttributeMaxDynamicSharedMemorySize, SMEM_BYTES);

    dim3 tb(32, 32);
    // ---- weight transposes + splits ----
    tsplit_kernel<<<dim3(Ii/32, Dm/32), tb>>>(Wq1, wq1h, wq1l, Dm, Ii);
    tsplit_kernel<<<dim3(Ii/32, Dm/32), tb>>>(Wk1, wk1h, wk1l, Dm, Ii);
    tsplit_kernel<<<dim3(Ii/32, Dm/32), tb>>>(Wv1, wv1h, wv1l, Dm, Ii);
    tsplit_kernel<<<dim3(Dm/32, Ii/32), tb>>>(Wo1, wo1h, wo1l, Ii, Dm);
    tsplit_kernel<<<dim3(Ii/32, Dm/32), tb>>>(Wq2, wq2h, wq2l, Dm, Ii);
    tsplit_kernel<<<dim3(Ii/32, DCc/32), tb>>>(Wk2, wk2h, wk2l, DCc, Ii);
    tsplit_kernel<<<dim3(Ii/32, DCc/32), tb>>>(Wv2, wv2h, wv2l, DCc, Ii);
    tsplit_kernel<<<dim3(Dm/32, Ii/32), tb>>>(Wo2, wo2h, wo2l, Ii, Dm);
    tsplit_kernel<<<dim3((2*FFd)/32, Dm/32), tb>>>(Wff1, wf1h, wf1l, Dm, 2*FFd);
    tsplit_kernel<<<dim3(Dm/32, FFd/32), tb>>>(Wff2, wf2h, wf2l, FFd, Dm);
    split_kernel<<<(BM2*DCc + 255)/256, 256>>>(ctx, ctxh, ctxl, (long long)BM2*DCc);

    // ================= block 1: self-attention =================
    ln_split_kernel<<<BN, 256>>>(x, ln1_g, ln1_b, lnh, lnl);

    mma_gemm<<<ggrid(BN, Ii, 1), 256, SMEM_BYTES>>>(lnh, lnl, wq1h, wq1l, nullptr, nullptr,
        nullptr, qh, ql, BN, Ii, Dm, Dm, Dm, Ii, 0,0,0,0,0,0, 1, 1.f);
    mma_gemm<<<ggrid(BN, Ii, 1), 256, SMEM_BYTES>>>(lnh, lnl, wk1h, wk1l, nullptr, nullptr,
        nullptr, kh, kl, BN, Ii, Dm, Dm, Dm, Ii, 0,0,0,0,0,0, 1, 1.f);
    mma_gemm<<<ggrid(BN, Ii, 1), 256, SMEM_BYTES>>>(lnh, lnl, wv1h, wv1l, nullptr, nullptr,
        v, nullptr, nullptr, BN, Ii, Dm, Dm, Dm, Ii, 0,0,0,0,0,0, 1, 1.f);

    head_tsplit_kernel<<<dim3(Ntok/32, 2, BHh), tb>>>(v, vth, vtl, Ntok, Ntok);

    // sim = Q K^T * SCALE
    mma_gemm<<<ggrid(Ntok, Ntok, BHh), 256, SMEM_BYTES>>>(qh, ql, kh, kl, nullptr, nullptr,
        sim, nullptr, nullptr, Ntok, Ntok, DHd, Ii, Ii, Ntok,
        (long long)Ntok*Ii, 64, (long long)Ntok*Ii, 64,
        (long long)Hh*Ntok*Ntok, (long long)Ntok*Ntok, Hh, SCALE);

    softmax_split_kernel<8><<<BHh*Ntok, 256>>>(sim, Ph, Pl, Ntok, Ntok, Ntok);

    // att = P @ V
    mma_gemm<<<ggrid(Ntok, DHd, BHh), 256, SMEM_BYTES>>>(Ph, Pl, vth, vtl, nullptr, nullptr,
        nullptr, atth, attl, Ntok, DHd, Ntok, Ntok, Ntok, Ii,
        (long long)Hh*Ntok*Ntok, (long long)Ntok*Ntok,
        (long long)Hh*DHd*Ntok, (long long)DHd*Ntok,
        (long long)Ntok*Ii, 64, Hh, 1.f);

    // x1 = att @ Wo1 + bo1 + x
    mma_gemm<<<ggrid(BN, Dm, 1), 256, SMEM_BYTES>>>(atth, attl, wo1h, wo1l, bo1, x,
        x1, nullptr, nullptr, BN, Dm, Ii, Ii, Ii, Dm, 0,0,0,0,0,0, 1, 1.f);

    // ================= block 2: cross-attention =================
    ln_split_kernel<<<BN, 256>>>(x1, ln2_g, ln2_b, lnh, lnl);

    mma_gemm<<<ggrid(BN, Ii, 1), 256, SMEM_BYTES>>>(lnh, lnl, wq2h, wq2l, nullptr, nullptr,
        nullptr, qh, ql, BN, Ii, Dm, Dm, Dm, Ii, 0,0,0,0,0,0, 1, 1.f);
    mma_gemm<<<ggrid(BM2, Ii, 1), 256, SMEM_BYTES>>>(ctxh, ctxl, wk2h, wk2l, nullptr, nullptr,
        nullptr, kh, kl, BM2, Ii, DCc, DCc, DCc, Ii, 0,0,0,0,0,0, 1, 1.f);
    mma_gemm<<<ggrid(BM2, Ii, 1), 256, SMEM_BYTES>>>(ctxh, ctxl, wv2h, wv2l, nullptr, nullptr,
        v, nullptr, nullptr, BM2, Ii, DCc, DCc, DCc, Ii, 0,0,0,0,0,0, 1, 1.f);

    head_tsplit_kernel<<<dim3((MctxP+31)/32, 2, BHh), tb>>>(v, vth, vtl, Mctx, MctxP);

    // sim2 = Q2 K2^T * SCALE   (C ld = MctxP)
    mma_gemm<<<ggrid(Ntok, Mctx, BHh), 256, SMEM_BYTES>>>(qh, ql, kh, kl, nullptr, nullptr,
        sim, nullptr, nullptr, Ntok, Mctx, DHd, Ii, Ii, MctxP,
        (long long)Ntok*Ii, 64, (long long)Mctx*Ii, 64,
        (long long)Hh*Ntok*MctxP, (long long)Ntok*MctxP, Hh, SCALE);

    softmax_split_kernel<1><<<BHh*Ntok, 256>>>(sim, Ph, Pl, Mctx, MctxP, MctxP);

    // att = P2 @ V2  (K = MctxP, zero-padded)
    mma_gemm<<<ggrid(Ntok, DHd, BHh), 256, SMEM_BYTES>>>(Ph, Pl, vth, vtl, nullptr, nullptr,
        nullptr, atth, attl, Ntok, DHd, MctxP, MctxP, MctxP, Ii,
        (long long)Hh*Ntok*MctxP, (long long)Ntok*MctxP,
        (long long)Hh*DHd*MctxP, (long long)DHd*MctxP,
        (long long)Ntok*Ii, 64, Hh, 1.f);

    // x2 = att @ Wo2 + bo2 + x1
    mma_gemm<<<ggrid(BN, Dm, 1), 256, SMEM_BYTES>>>(atth, attl, wo2h, wo2l, bo2, x1,
        x2, nullptr, nullptr, BN, Dm, Ii, Ii, Ii, Dm, 0,0,0,0,0,0, 1, 1.f);

    // ================= block 3: GEGLU FF =================
    ln_split_kernel<<<BN, 256>>>(x2, ln3_g, ln3_b, lnh, lnl);

    mma_gemm<<<ggrid(BN, 2*FFd, 1), 256, SMEM_BYTES>>>(lnh, lnl, wf1h, wf1l, bff1, nullptr,
        hg, nullptr, nullptr, BN, 2*FFd, Dm, Dm, Dm, 2*FFd, 0,0,0,0,0,0, 1, 1.f);

    geglu_split_kernel<<<(int)(((long long)BN*FFd + 255)/256), 256>>>(hg, ffh, ffl);

    mma_gemm<<<ggrid(BN, Dm, 1), 256, SMEM_BYTES>>>(ffh, ffl, wf2h, wf2l, bff2, x2,
        out, nullptr, nullptr, BN, Dm, FFd, FFd, FFd, Dm, 0,0,0,0,0,0, 1, 1.f);
}

// round 4
// speedup vs baseline: 3.7527x; 1.2056x over previous
#include <cuda_runtime.h>
#include <cuda_fp16.h>
#include <math.h>
#include <stdint.h>

// ---------------------------------------------------------------------------
// Problem constants
// ---------------------------------------------------------------------------
#define Bsz   2
#define Ntok  2048
#define Dm    1024
#define Hh    16
#define DHd   64
#define Ii    1024
#define DCc   768
#define Mctx  77
#define MctxP 80
#define FFd   4096
#define BN    (Bsz*Ntok)
#define BM2   (Bsz*Mctx)
#define BHh   (Bsz*Hh)
#define SCALE 0.125f

// ---------------------------------------------------------------------------
// Device scratch
// ---------------------------------------------------------------------------
#define DEVARR(name, type, count) __device__ __align__(16) type name[(size_t)(count)]

DEVARR(g_lnh,  half, BN*Dm);   DEVARR(g_lnl,  half, BN*Dm);
DEVARR(g_qh,   half, BN*Ii);   DEVARR(g_ql,   half, BN*Ii);
DEVARR(g_kh,   half, BN*Ii);   DEVARR(g_kl,   half, BN*Ii);
DEVARR(g_v,    float, BN*Ii);
DEVARR(g_vth,  half, BHh*DHd*Ntok); DEVARR(g_vtl, half, BHh*DHd*Ntok);
DEVARR(g_sim,  float, (size_t)BHh*Ntok*MctxP);            // cross-attn only
DEVARR(g_Ph,   half, (size_t)BHh*Ntok*MctxP); DEVARR(g_Pl, half, (size_t)BHh*Ntok*MctxP);
DEVARR(g_atth, half, BN*Ii);   DEVARR(g_attl, half, BN*Ii);
DEVARR(g_x1,   float, BN*Dm);  DEVARR(g_x2,   float, BN*Dm);
DEVARR(g_ctxh, half, BM2*DCc); DEVARR(g_ctxl, half, BM2*DCc);
DEVARR(g_hg,   float, (size_t)BN*2*FFd);
DEVARR(g_ffh,  half, (size_t)BN*FFd); DEVARR(g_ffl, half, (size_t)BN*FFd);
// transposed/split weights [N x K]
DEVARR(g_wq1h, half, Dm*Ii);  DEVARR(g_wq1l, half, Dm*Ii);
DEVARR(g_wk1h, half, Dm*Ii);  DEVARR(g_wk1l, half, Dm*Ii);
DEVARR(g_wv1h, half, Dm*Ii);  DEVARR(g_wv1l, half, Dm*Ii);
DEVARR(g_wo1h, half, Dm*Ii);  DEVARR(g_wo1l, half, Dm*Ii);
DEVARR(g_wq2h, half, Dm*Ii);  DEVARR(g_wq2l, half, Dm*Ii);
DEVARR(g_wk2h, half, DCc*Ii); DEVARR(g_wk2l, half, DCc*Ii);
DEVARR(g_wv2h, half, DCc*Ii); DEVARR(g_wv2l, half, DCc*Ii);
DEVARR(g_wo2h, half, Dm*Ii);  DEVARR(g_wo2l, half, Dm*Ii);
DEVARR(g_wf1h, half, (size_t)Dm*2*FFd); DEVARR(g_wf1l, half, (size_t)Dm*2*FFd);
DEVARR(g_wf2h, half, (size_t)FFd*Dm);   DEVARR(g_wf2l, half, (size_t)FFd*Dm);

// ---------------------------------------------------------------------------
// Helpers
// ---------------------------------------------------------------------------
__device__ __forceinline__ uint32_t smem_u32(const void* p) {
    uint32_t a;
    asm("{ .reg .u64 t; cvta.to.shared.u64 t, %1; cvt.u32.u64 %0, t; }" : "=r"(a) : "l"(p));
    return a;
}
__device__ __forceinline__ void split2(float x, half& h, half& l) {
    h = __float2half_rn(x);
    l = __float2half_rn(x - __half2float(h));
}

#define LDSM4(r0, r1, r2, r3, addr) \
    asm volatile("ldmatrix.sync.aligned.m8n8.x4.shared.b16 {%0,%1,%2,%3}, [%4];" \
        : "=r"(r0), "=r"(r1), "=r"(r2), "=r"(r3) : "r"(addr))

#define MMA16816(c, a, b0, b1) \
    asm volatile("mma.sync.aligned.m16n8k16.row.col.f32.f16.f16.f32 " \
        "{%0,%1,%2,%3}, {%4,%5,%6,%7}, {%8,%9}, {%0,%1,%2,%3};" \
        : "+f"((c)[0]), "+f"((c)[1]), "+f"((c)[2]), "+f"((c)[3]) \
        : "r"((a)[0]), "r"((a)[1]), "r"((a)[2]), "r"((a)[3]), "r"(b0), "r"(b1))

#define CP_ASYNC16(dst, src) \
    asm volatile("cp.async.cg.shared.global [%0], [%1], 16;" :: "r"(dst), "l"(src) : "memory")
#define CP_COMMIT() asm volatile("cp.async.commit_group;" ::: "memory")

// ---------------------------------------------------------------------------
// mma.sync fp16-split GEMM (unchanged from round 3)
// ---------------------------------------------------------------------------
#define PITCH   40
#define TILE_H  (128*PITCH)
#define STAGE_H (4*TILE_H)
#define SMEM_BYTES (2*STAGE_H*2)

__global__ void __launch_bounds__(256) mma_gemm(
    const half* __restrict__ Ah_, const half* __restrict__ Al_,
    const half* __restrict__ Bh_, const half* __restrict__ Bl_,
    const float* __restrict__ bias, const float* __restrict__ resid,
    float* __restrict__ C, half* __restrict__ Ch, half* __restrict__ Cl,
    int M, int N, int K, int lda, int ldb, int ldc,
    long long aO, long long aI, long long bO, long long bI,
    long long cO, long long cI, int nInner, float alpha)
{
    extern __shared__ half sm[];
    uint32_t smBase = smem_u32(sm);
    int tid = threadIdx.x, lane = tid & 31, wid = tid >> 5;
    int warpM = wid >> 1, warpN = wid & 1;

    int z = blockIdx.z, zo = z / nInner, zi = z % nInner;
    const half* Ahp = Ah_ + (long long)zo * aO + (long long)zi * aI;
    const half* Alp = Al_ + (long long)zo * aO + (long long)zi * aI;
    const half* Bhp = Bh_ + (long long)zo * bO + (long long)zi * bI;
    const half* Blp = Bl_ + (long long)zo * bO + (long long)zi * bI;
    long long offC = (long long)zo * cO + (long long)zi * cI;

    int rowBase = blockIdx.y * 128, colBase = blockIdx.x * 128;

    float acc[2][8][4];
    #pragma unroll
    for (int i = 0; i < 2; i++)
        #pragma unroll
        for (int j = 0; j < 8; j++)
            #pragma unroll
            for (int e = 0; e < 4; e++) acc[i][j][e] = 0.f;

    int nc = (K + 31) >> 5;

    auto load_stage = [&](int c, int s) {
        int k0 = c << 5;
        #pragma unroll
        for (int i = 0; i < 8; i++) {
            int seg  = tid + (i << 8);
            int tile = seg >> 9;
            int w    = seg & 511;
            int row  = w >> 2;
            int cs   = (w & 3) << 3;
            bool isA = tile < 2;
            const half* base = (tile == 0) ? Ahp : (tile == 1) ? Alp
                             : (tile == 2) ? Bhp : Blp;
            int ld  = isA ? lda : ldb;
            int gr  = (isA ? rowBase : colBase) + row;
            int gk  = k0 + cs;
            bool ok = (gr < (isA ? M : N)) && (gk + 8 <= K);
            const half* src = ok ? (base + (size_t)gr * ld + gk) : base;
            uint32_t dst = smBase + (uint32_t)(((s * 4 + tile) * TILE_H + row * PITCH + cs) * 2);
            uint32_t sz = ok ? 16u : 0u;
            asm volatile("cp.async.cg.shared.global [%0], [%1], 16, %2;"
                         :: "r"(dst), "l"(src), "r"(sz) : "memory");
        }
    };

    int aRow = (lane & 7) + ((lane >> 3) & 1) * 8;
    int aCg  = (lane >> 4) * 8;
    int bRow = (lane & 7) + (lane >> 4) * 8;
    int bCg  = ((lane >> 3) & 1) * 8;

    auto compute_stage = [&](int s) {
        uint32_t sBase = smBase + (uint32_t)(s * STAGE_H * 2);
        #pragma unroll
        for (int ks = 0; ks < 2; ks++) {
            uint32_t ah[2][4], al[2][4];
            #pragma unroll
            for (int mm = 0; mm < 2; mm++) {
                uint32_t addr = sBase + (uint32_t)(((warpM * 32 + mm * 16 + aRow) * PITCH + ks * 16 + aCg) * 2);
                LDSM4(ah[mm][0], ah[mm][1], ah[mm][2], ah[mm][3], addr);
                LDSM4(al[mm][0], al[mm][1], al[mm][2], al[mm][3], addr + TILE_H * 2);
            }
            #pragma unroll
            for (int nn = 0; nn < 4; nn++) {
                uint32_t baddr = sBase + (uint32_t)((2 * TILE_H + (warpN * 64 + nn * 16 + bRow) * PITCH + ks * 16 + bCg) * 2);
                uint32_t bh[4], bl[4];
                LDSM4(bh[0], bh[1], bh[2], bh[3], baddr);
                LDSM4(bl[0], bl[1], bl[2], bl[3], baddr + TILE_H * 2);
                #pragma unroll
                for (int mm = 0; mm < 2; mm++) {
                    MMA16816(acc[mm][2 * nn],     ah[mm], bh[0], bh[1]);
                    MMA16816(acc[mm][2 * nn + 1], ah[mm], bh[2], bh[3]);
                    MMA16816(acc[mm][2 * nn],     ah[mm], bl[0], bl[1]);
                    MMA16816(acc[mm][2 * nn + 1], ah[mm], bl[2], bl[3]);
                    MMA16816(acc[mm][2 * nn],     al[mm], bh[0], bh[1]);
                    MMA16816(acc[mm][2 * nn + 1], al[mm], bh[2], bh[3]);
                }
            }
        }
    };

    load_stage(0, 0);
    CP_COMMIT();
    for (int c = 0; c < nc; c++) {
        if (c + 1 < nc) load_stage(c + 1, (c + 1) & 1);
        CP_COMMIT();
        asm volatile("cp.async.wait_group 1;" ::: "memory");
        __syncthreads();
        compute_stage(c & 1);
        __syncthreads();
    }

    #pragma unroll
    for (int mm = 0; mm < 2; mm++) {
        #pragma unroll
        for (int nf = 0; nf < 8; nf++) {
            int r  = rowBase + warpM * 32 + mm * 16 + (lane >> 2);
            int cc = colBase + warpN * 64 + nf * 8 + (lane & 3) * 2;
            #pragma unroll
            for (int e = 0; e < 4; e++) {
                int rr = r + (e >> 1) * 8;
                int gc = cc + (e & 1);
                if (rr < M && gc < N) {
                    float v = acc[mm][nf][e] * alpha;
                    if (bias) v += bias[gc];
                    size_t idx = (size_t)offC + (size_t)rr * ldc + gc;
                    if (resid) v += resid[idx];
                    if (C) C[idx] = v;
                    if (Ch) { half h, l; split2(v, h, l); Ch[idx] = h; Cl[idx] = l; }
                }
            }
        }
    }
}

// ---------------------------------------------------------------------------
// Fused flash self-attention.
// grid (Ntok/128, BHh), 256 threads, warp = 16 q rows.
// Q/K pre-scaled: Q GEMM used alpha=SCALE. Q,K split [BN x Ii] (head col h*64).
// V split transposed per head: vt[bh][d][key].
// Out: atth/attl [BN x Ii].
// ---------------------------------------------------------------------------
#define FA_PITCH  72              // halves pitch for [128 x 64] tiles
#define FA_VPITCH 136             // halves pitch for [64 x 128] tiles
#define FA_QT     (128*FA_PITCH)  // 9216 halves
#define FA_VT     (64*FA_VPITCH)  // 8704 halves
#define FA_KBASE  (2*FA_QT)
#define FA_VBASE  (2*FA_QT + 4*FA_QT)
#define FA_SMEM_H (FA_VBASE + 4*FA_VT)
#define FA_SMEM_BYTES (FA_SMEM_H*2)   // 180224

__global__ void __launch_bounds__(256) flash_attn(
    const half* __restrict__ qh, const half* __restrict__ ql,
    const half* __restrict__ kh, const half* __restrict__ kl,
    const half* __restrict__ vth, const half* __restrict__ vtl,
    half* __restrict__ atth, half* __restrict__ attl)
{
    extern __shared__ half sm[];
    uint32_t smBase = smem_u32(sm);
    int tid = threadIdx.x, lane = tid & 31, wid = tid >> 5;

    int bh = blockIdx.y;
    int b = bh >> 4, h = bh & 15;
    int q0 = blockIdx.x * 128;
    int qg0 = b * Ntok + q0;
    int kg0 = b * Ntok;
    int hcol = h * 64;
    size_t vbase = (size_t)bh * 64 * Ntok;

    // ---- loaders ----
    auto ldQ = [&]() {
        #pragma unroll
        for (int i = 0; i < 8; i++) {
            int seg = tid + (i << 8);           // 0..2047
            int hl = seg >> 10;
            int w = seg & 1023;
            int row = w >> 3;
            int cs = (w & 7) << 3;
            const half* src = (hl ? ql : qh) + (size_t)(qg0 + row) * Ii + hcol + cs;
            uint32_t dst = smBase + (uint32_t)((hl * FA_QT + row * FA_PITCH + cs) * 2);
            CP_ASYNC16(dst, src);
        }
    };
    auto ldKV = [&](int chunk, int s) {
        int key0 = chunk << 7;
        #pragma unroll
        for (int i = 0; i < 16; i++) {
            int seg = tid + (i << 8);           // 0..4095
            int t = seg >> 10;                  // 0 Kh, 1 Kl, 2 Vh, 3 Vl
            int w = seg & 1023;
            if (t < 2) {
                int row = w >> 3;
                int cs = (w & 7) << 3;
                const half* src = (t ? kl : kh) + (size_t)(kg0 + key0 + row) * Ii + hcol + cs;
                uint32_t dst = smBase + (uint32_t)((FA_KBASE + (s * 2 + t) * FA_QT + row * FA_PITCH + cs) * 2);
                CP_ASYNC16(dst, src);
            } else {
                int row = w >> 4;
                int cs = (w & 15) << 3;
                const half* src = ((t == 3) ? vtl : vth) + vbase + (size_t)row * Ntok + key0 + cs;
                uint32_t dst = smBase + (uint32_t)((FA_VBASE + (s * 2 + (t - 2)) * FA_VT + row * FA_VPITCH + cs) * 2);
                CP_ASYNC16(dst, src);
            }
        }
    };

    int aRow = (lane & 7) + ((lane >> 3) & 1) * 8;
    int aCg  = (lane >> 4) * 8;
    int bRow = (lane & 7) + (lane >> 4) * 8;
    int bCg  = ((lane >> 3) & 1) * 8;

    float O[8][4];
    #pragma unroll
    for (int i = 0; i < 8; i++)
        #pragma unroll
        for (int e = 0; e < 4; e++) O[i][e] = 0.f;
    float M0 = -1e30f, M1 = -1e30f, L0 = 0.f, L1 = 0.f;

    ldQ(); ldKV(0, 0);
    CP_COMMIT();
    ldKV(1, 1);
    CP_COMMIT();

    for (int c = 0; c < 16; c++) {
        if (c < 15) asm volatile("cp.async.wait_group 1;" ::: "memory");
        else        asm volatile("cp.async.wait_group 0;" ::: "memory");
        __syncthreads();

        int s = c & 1;
        // ---- S = Q K^T (pre-scaled), 16x128 per warp ----
        float S[16][4];
        #pragma unroll
        for (int i = 0; i < 16; i++)
            #pragma unroll
            for (int e = 0; e < 4; e++) S[i][e] = 0.f;

        uint32_t kTile = smBase + (uint32_t)((FA_KBASE + s * 2 * FA_QT) * 2);
        #pragma unroll
        for (int ks = 0; ks < 4; ks++) {
            uint32_t aH[4], aL[4];
            uint32_t addrA = smBase + (uint32_t)(((wid * 16 + aRow) * FA_PITCH + ks * 16 + aCg) * 2);
            LDSM4(aH[0], aH[1], aH[2], aH[3], addrA);
            LDSM4(aL[0], aL[1], aL[2], aL[3], addrA + FA_QT * 2);
            #pragma unroll
            for (int nn = 0; nn < 8; nn++) {
                uint32_t addrB = kTile + (uint32_t)(((nn * 16 + bRow) * FA_PITCH + ks * 16 + bCg) * 2);
                uint32_t bH[4], bL[4];
                LDSM4(bH[0], bH[1], bH[2], bH[3], addrB);
                LDSM4(bL[0], bL[1], bL[2], bL[3], addrB + FA_QT * 2);
                MMA16816(S[2 * nn],     aH, bH[0], bH[1]);
                MMA16816(S[2 * nn + 1], aH, bH[2], bH[3]);
                MMA16816(S[2 * nn],     aH, bL[0], bL[1]);
                MMA16816(S[2 * nn + 1], aH, bL[2], bL[3]);
                MMA16816(S[2 * nn],     aL, bH[0], bH[1]);
                MMA16816(S[2 * nn + 1], aL, bH[2], bH[3]);
            }
        }

        // ---- online softmax ----
        float cm0 = -1e30f, cm1 = -1e30f;
        #pragma unroll
        for (int i = 0; i < 16; i++) {
            cm0 = fmaxf(cm0, fmaxf(S[i][0], S[i][1]));
            cm1 = fmaxf(cm1, fmaxf(S[i][2], S[i][3]));
        }
        #pragma unroll
        for (int o = 1; o <= 2; o <<= 1) {
            cm0 = fmaxf(cm0, __shfl_xor_sync(0xffffffffu, cm0, o));
            cm1 = fmaxf(cm1, __shfl_xor_sync(0xffffffffu, cm1, o));
        }
        float nM0 = fmaxf(M0, cm0), nM1 = fmaxf(M1, cm1);
        float f0 = __expf(M0 - nM0), f1 = __expf(M1 - nM1);
        M0 = nM0; M1 = nM1;
        #pragma unroll
        for (int i = 0; i < 8; i++) {
            O[i][0] *= f0; O[i][1] *= f0; O[i][2] *= f1; O[i][3] *= f1;
        }
        float l0 = 0.f, l1 = 0.f;
        #pragma unroll
        for (int i = 0; i < 16; i++) {
            S[i][0] = __expf(S[i][0] - nM0);
            S[i][1] = __expf(S[i][1] - nM0);
            S[i][2] = __expf(S[i][2] - nM1);
            S[i][3] = __expf(S[i][3] - nM1);
            l0 += S[i][0] + S[i][1];
            l1 += S[i][2] + S[i][3];
        }
        #pragma unroll
        for (int o = 1; o <= 2; o <<= 1) {
            l0 += __shfl_xor_sync(0xffffffffu, l0, o);
            l1 += __shfl_xor_sync(0xffffffffu, l1, o);
        }
        L0 = L0 * f0 + l0;
        L1 = L1 * f1 + l1;

        // ---- O += P @ V ----
        uint32_t vTile = smBase + (uint32_t)((FA_VBASE + s * 2 * FA_VT) * 2);
        #pragma unroll
        for (int kk = 0; kk < 8; kk++) {
            uint32_t PhF[4], PlF[4];
            #pragma unroll
            for (int u = 0; u < 2; u++) {          // u=0: tile 2kk (rows r/r+8 in [0],[1]), u=1: tile 2kk+1
                int t = 2 * kk + u;
                half2 h01 = __floats2half2_rn(S[t][0], S[t][1]);
                half2 h23 = __floats2half2_rn(S[t][2], S[t][3]);
                float r0a = S[t][0] - __low2float(h01);
                float r0b = S[t][1] - __high2float(h01);
                float r1a = S[t][2] - __low2float(h23);
                float r1b = S[t][3] - __high2float(h23);
                half2 lo01 = __floats2half2_rn(r0a, r0b);
                half2 lo23 = __floats2half2_rn(r1a, r1b);
                PhF[2 * u]     = *reinterpret_cast<uint32_t*>(&h01);
                PhF[2 * u + 1] = *reinterpret_cast<uint32_t*>(&h23);
                PlF[2 * u]     = *reinterpret_cast<uint32_t*>(&lo01);
                PlF[2 * u + 1] = *reinterpret_cast<uint32_t*>(&lo23);
            }
            #pragma unroll
            for (int nn = 0; nn < 4; nn++) {
                uint32_t addrV = vTile + (uint32_t)(((nn * 16 + bRow) * FA_VPITCH + kk * 16 + bCg) * 2);
                uint32_t vH[4], vL[4];
                LDSM4(vH[0], vH[1], vH[2], vH[3], addrV);
                LDSM4(vL[0], vL[1], vL[2], vL[3], addrV + FA_VT * 2);
                MMA16816(O[2 * nn],     PhF, vH[0], vH[1]);
                MMA16816(O[2 * nn + 1], PhF, vH[2], vH[3]);
                MMA16816(O[2 * nn],     PlF, vH[0], vH[1]);
                MMA16816(O[2 * nn + 1], PlF, vH[2], vH[3]);
                MMA16816(O[2 * nn],     PhF, vL[0], vL[1]);
                MMA16816(O[2 * nn + 1], PhF, vL[2], vL[3]);
            }
        }

        __syncthreads();
        if (c + 2 < 16) { ldKV(c + 2, s); CP_COMMIT(); }
    }

    // ---- finalize: O / L, split store ----
    float inv0 = 1.f / L0, inv1 = 1.f / L1;
    int r0 = qg0 + wid * 16 + (lane >> 2);
    int r1 = r0 + 8;
    #pragma unroll
    for (int nf = 0; nf < 8; nf++) {
        int d0 = nf * 8 + (lane & 3) * 2;
        float v00 = O[nf][0] * inv0, v01 = O[nf][1] * inv0;
        float v10 = O[nf][2] * inv1, v11 = O[nf][3] * inv1;
        half h0, l0h, h1, l1h, h2a, l2, h3, l3;
        split2(v00, h0, l0h); split2(v01, h1, l1h);
        split2(v10, h2a, l2); split2(v11, h3, l3);
        *reinterpret_cast<half2*>(atth + (size_t)r0 * Ii + hcol + d0) = __halves2half2(h0, h1);
        *reinterpret_cast<half2*>(attl + (size_t)r0 * Ii + hcol + d0) = __halves2half2(l0h, l1h);
        *reinterpret_cast<half2*>(atth + (size_t)r1 * Ii + hcol + d0) = __halves2half2(h2a, h3);
        *reinterpret_cast<half2*>(attl + (size_t)r1 * Ii + hcol + d0) = __halves2half2(l2, l3);
    }
}

// ---------------------------------------------------------------------------
// LayerNorm -> split fp16
// ---------------------------------------------------------------------------
__global__ __launch_bounds__(256) void ln_split_kernel(
    const float* __restrict__ x, const float* __restrict__ g, const float* __restrict__ b,
    half* __restrict__ oh, half* __restrict__ ol)
{
    size_t row = blockIdx.x;
    const float* xr = x + row * Dm;
    __shared__ float red[256];
    int t = threadIdx.x;
    float v[4];
    float s = 0.f;
    #pragma unroll
    for (int j = 0; j < 4; j++) { v[j] = xr[t + j * 256]; s += v[j]; }
    red[t] = s; __syncthreads();
    for (int o = 128; o > 0; o >>= 1) { if (t < o) red[t] += red[t + o]; __syncthreads(); }
    float mean = red[0] * (1.f / Dm);
    __syncthreads();
    float s2 = 0.f;
    #pragma unroll
    for (int j = 0; j < 4; j++) { float d = v[j] - mean; s2 += d * d; }
    red[t] = s2; __syncthreads();
    for (int o = 128; o > 0; o >>= 1) { if (t < o) red[t] += red[t + o]; __syncthreads(); }
    float inv = rsqrtf(red[0] * (1.f / Dm) + 1e-5f);
    #pragma unroll
    for (int j = 0; j < 4; j++) {
        int i = t + j * 256;
        float val = (v[j] - mean) * inv * g[i] + b[i];
        half h, l; split2(val, h, l);
        oh[row * Dm + i] = h; ol[row * Dm + i] = l;
    }
}

// ---------------------------------------------------------------------------
// Softmax -> split fp16 (cross-attn, 77 cols padded to 80)
// ---------------------------------------------------------------------------
__global__ __launch_bounds__(256) void softmax_split_kernel(
    const float* __restrict__ s, half* __restrict__ ph, half* __restrict__ pl,
    int cols, int ldin, int ldout)
{
    size_t row = blockIdx.x;
    const float* r = s + row * (size_t)ldin;
    __shared__ float red[256];
    int t = threadIdx.x;
    float v;
    float m = -INFINITY;
    v = (t < cols) ? r[t] : -INFINITY;
    m = v;
    red[t] = m; __syncthreads();
    for (int o = 128; o > 0; o >>= 1) { if (t < o) red[t] = fmaxf(red[t], red[t + o]); __syncthreads(); }
    m = red[0]; __syncthreads();
    float e = (t < cols) ? __expf(v - m) : 0.f;
    red[t] = e; __syncthreads();
    for (int o = 128; o > 0; o >>= 1) { if (t < o) red[t] += red[t + o]; __syncthreads(); }
    float inv = 1.f / red[0];
    if (t < ldout) {
        half h, l; split2(e * inv, h, l);
        ph[row * (size_t)ldout + t] = h;
        pl[row * (size_t)ldout + t] = l;
    }
}

// ---------------------------------------------------------------------------
// GEGLU -> split fp16
// ---------------------------------------------------------------------------
__global__ __launch_bounds__(256) void geglu_split_kernel(
    const float* __restrict__ hg, half* __restrict__ oh, half* __restrict__ ol)
{
    size_t idx = (size_t)blockIdx.x * 256 + threadIdx.x;
    if (idx >= (size_t)BN * FFd) return;
    size_t r = idx / FFd; int c = (int)(idx % FFd);
    float h = hg[r * (2 * FFd) + c];
    float g = hg[r * (2 * FFd) + FFd + c];
    float gl = 0.5f * g * (1.f + erff(g * 0.70710678118654752440f));
    half hh, ll; split2(h * gl, hh, ll);
    oh[idx] = hh; ol[idx] = ll;
}

// ---------------------------------------------------------------------------
// Plain split
// ---------------------------------------------------------------------------
__global__ __launch_bounds__(256) void split_kernel(
    const float* __restrict__ src, half* __restrict__ dh, half* __restrict__ dl, long long n)
{
    long long i = (long long)blockIdx.x * 256 + threadIdx.x;
    if (i >= n) return;
    half h, l; split2(src[i], h, l);
    dh[i] = h; dl[i] = l;
}

// ---------------------------------------------------------------------------
// Transpose + split: src [R x C] fp32 -> dst [C x R] fp16 hi/lo
// ---------------------------------------------------------------------------
__global__ __launch_bounds__(1024) void tsplit_kernel(
    const float* __restrict__ src, half* __restrict__ dh, half* __restrict__ dl, int R, int C)
{
    __shared__ float tile[32][33];
    int c0 = blockIdx.x * 32, r0 = blockIdx.y * 32;
    int tx = threadIdx.x, ty = threadIdx.y;
    int r = r0 + ty, c = c0 + tx;
    tile[ty][tx] = (r < R && c < C) ? src[(size_t)r * C + c] : 0.f;
    __syncthreads();
    int rr = r0 + tx, cc = c0 + ty;
    if (rr < R && cc < C) {
        half h, l; split2(tile[tx][ty], h, l);
        dh[(size_t)cc * R + rr] = h;
        dl[(size_t)cc * R + rr] = l;
    }
}

// ---------------------------------------------------------------------------
// Per-head transpose+split of V
// ---------------------------------------------------------------------------
__global__ __launch_bounds__(1024) void head_tsplit_kernel(
    const float* __restrict__ src, half* __restrict__ dh, half* __restrict__ dl,
    int T, int Tpad)
{
    __shared__ float tile[32][33];
    int zh = blockIdx.z;
    int b = zh >> 4, h = zh & 15;
    int tx = threadIdx.x, ty = threadIdx.y;
    int t0 = blockIdx.x * 32, d0 = blockIdx.y * 32;
    int t = t0 + ty, d = d0 + tx;
    tile[ty][tx] = (t < T) ? src[((size_t)b * T + t) * 1024 + h * 64 + d] : 0.f;
    __syncthreads();
    int dd = d0 + ty, tt = t0 + tx;
    if (tt < Tpad) {
        half hh, ll; split2(tile[tx][ty], hh, ll);
        size_t base = (size_t)zh * 64 * Tpad + (size_t)dd * Tpad + tt;
        dh[base] = hh; dl[base] = ll;
    }
}

// ---------------------------------------------------------------------------
// Orchestration
// ---------------------------------------------------------------------------
static inline dim3 ggrid(int M, int N, int z) { return dim3((N + 127) / 128, (M + 127) / 128, z); }

#define SYM(p, s) cudaGetSymbolAddress((void**)&p, s)

extern "C" void kernel_launch(void* const* d_in, const int* in_sizes, int n_in,
                              void* d_out, int out_size)
{
    const float* x     = (const float*)d_in[0];
    const float* ctx   = (const float*)d_in[1];
    const float* ln1_g = (const float*)d_in[2];
    const float* ln1_b = (const float*)d_in[3];
    const float* ln2_g = (const float*)d_in[4];
    const float* ln2_b = (const float*)d_in[5];
    const float* ln3_g = (const float*)d_in[6];
    const float* ln3_b = (const float*)d_in[7];
    const float* Wq1   = (const float*)d_in[8];
    const float* Wk1   = (const float*)d_in[9];
    const float* Wv1   = (const float*)d_in[10];
    const float* Wo1   = (const float*)d_in[11];
    const float* bo1   = (const float*)d_in[12];
    const float* Wq2   = (const float*)d_in[13];
    const float* Wk2   = (const float*)d_in[14];
    const float* Wv2   = (const float*)d_in[15];
    const float* Wo2   = (const float*)d_in[16];
    const float* bo2   = (const float*)d_in[17];
    const float* Wff1  = (const float*)d_in[18];
    const float* bff1  = (const float*)d_in[19];
    const float* Wff2  = (const float*)d_in[20];
    const float* bff2  = (const float*)d_in[21];
    float* out = (float*)d_out;

    half *lnh,*lnl,*qh,*ql,*kh,*kl,*vth,*vtl,*Ph,*Pl,*atth,*attl,*ctxh,*ctxl,*ffh,*ffl;
    half *wq1h,*wq1l,*wk1h,*wk1l,*wv1h,*wv1l,*wo1h,*wo1l;
    half *wq2h,*wq2l,*wk2h,*wk2l,*wv2h,*wv2l,*wo2h,*wo2l,*wf1h,*wf1l,*wf2h,*wf2l;
    float *v,*sim,*x1,*x2,*hg;
    SYM(lnh,g_lnh); SYM(lnl,g_lnl); SYM(qh,g_qh); SYM(ql,g_ql); SYM(kh,g_kh); SYM(kl,g_kl);
    SYM(v,g_v); SYM(vth,g_vth); SYM(vtl,g_vtl); SYM(sim,g_sim); SYM(Ph,g_Ph); SYM(Pl,g_Pl);
    SYM(atth,g_atth); SYM(attl,g_attl); SYM(x1,g_x1); SYM(x2,g_x2);
    SYM(ctxh,g_ctxh); SYM(ctxl,g_ctxl); SYM(hg,g_hg); SYM(ffh,g_ffh); SYM(ffl,g_ffl);
    SYM(wq1h,g_wq1h); SYM(wq1l,g_wq1l); SYM(wk1h,g_wk1h); SYM(wk1l,g_wk1l);
    SYM(wv1h,g_wv1h); SYM(wv1l,g_wv1l); SYM(wo1h,g_wo1h); SYM(wo1l,g_wo1l);
    SYM(wq2h,g_wq2h); SYM(wq2l,g_wq2l); SYM(wk2h,g_wk2h); SYM(wk2l,g_wk2l);
    SYM(wv2h,g_wv2h); SYM(wv2l,g_wv2l); SYM(wo2h,g_wo2h); SYM(wo2l,g_wo2l);
    SYM(wf1h,g_wf1h); SYM(wf1l,g_wf1l); SYM(wf2h,g_wf2h); SYM(wf2l,g_wf2l);

    cudaFuncSetAttribute(mma_gemm, cudaFuncAttributeMaxDynamicSharedMemorySize, SMEM_BYTES);
    cudaFuncSetAttribute(flash_attn, cudaFuncAttributeMaxDynamicSharedMemorySize, FA_SMEM_BYTES);

    dim3 tb(32, 32);
    // ---- weight transposes + splits ----
    tsplit_kernel<<<dim3(Ii/32, Dm/32), tb>>>(Wq1, wq1h, wq1l, Dm, Ii);
    tsplit_kernel<<<dim3(Ii/32, Dm/32), tb>>>(Wk1, wk1h, wk1l, Dm, Ii);
    tsplit_kernel<<<dim3(Ii/32, Dm/32), tb>>>(Wv1, wv1h, wv1l, Dm, Ii);
    tsplit_kernel<<<dim3(Dm/32, Ii/32), tb>>>(Wo1, wo1h, wo1l, Ii, Dm);
    tsplit_kernel<<<dim3(Ii/32, Dm/32), tb>>>(Wq2, wq2h, wq2l, Dm, Ii);
    tsplit_kernel<<<dim3(Ii/32, DCc/32), tb>>>(Wk2, wk2h, wk2l, DCc, Ii);
    tsplit_kernel<<<dim3(Ii/32, DCc/32), tb>>>(Wv2, wv2h, wv2l, DCc, Ii);
    tsplit_kernel<<<dim3(Dm/32, Ii/32), tb>>>(Wo2, wo2h, wo2l, Ii, Dm);
    tsplit_kernel<<<dim3((2*FFd)/32, Dm/32), tb>>>(Wff1, wf1h, wf1l, Dm, 2*FFd);
    tsplit_kernel<<<dim3(Dm/32, FFd/32), tb>>>(Wff2, wf2h, wf2l, FFd, Dm);
    split_kernel<<<(BM2*DCc + 255)/256, 256>>>(ctx, ctxh, ctxl, (long long)BM2*DCc);

    // ================= block 1: self-attention =================
    ln_split_kernel<<<BN, 256>>>(x, ln1_g, ln1_b, lnh, lnl);

    // q pre-scaled by SCALE
    mma_gemm<<<ggrid(BN, Ii, 1), 256, SMEM_BYTES>>>(lnh, lnl, wq1h, wq1l, nullptr, nullptr,
        nullptr, qh, ql, BN, Ii, Dm, Dm, Dm, Ii, 0,0,0,0,0,0, 1, SCALE);
    mma_gemm<<<ggrid(BN, Ii, 1), 256, SMEM_BYTES>>>(lnh, lnl, wk1h, wk1l, nullptr, nullptr,
        nullptr, kh, kl, BN, Ii, Dm, Dm, Dm, Ii, 0,0,0,0,0,0, 1, 1.f);
    mma_gemm<<<ggrid(BN, Ii, 1), 256, SMEM_BYTES>>>(lnh, lnl, wv1h, wv1l, nullptr, nullptr,
        v, nullptr, nullptr, BN, Ii, Dm, Dm, Dm, Ii, 0,0,0,0,0,0, 1, 1.f);

    head_tsplit_kernel<<<dim3(Ntok/32, 2, BHh), tb>>>(v, vth, vtl, Ntok, Ntok);

    // fused flash attention -> atth/attl
    flash_attn<<<dim3(Ntok/128, BHh), 256, FA_SMEM_BYTES>>>(qh, ql, kh, kl, vth, vtl, atth, attl);

    // x1 = att @ Wo1 + bo1 + x
    mma_gemm<<<ggrid(BN, Dm, 1), 256, SMEM_BYTES>>>(atth, attl, wo1h, wo1l, bo1, x,
        x1, nullptr, nullptr, BN, Dm, Ii, Ii, Ii, Dm, 0,0,0,0,0,0, 1, 1.f);

    // ================= block 2: cross-attention =================
    ln_split_kernel<<<BN, 256>>>(x1, ln2_g, ln2_b, lnh, lnl);

    mma_gemm<<<ggrid(BN, Ii, 1), 256, SMEM_BYTES>>>(lnh, lnl, wq2h, wq2l, nullptr, nullptr,
        nullptr, qh, ql, BN, Ii, Dm, Dm, Dm, Ii, 0,0,0,0,0,0, 1, SCALE);
    mma_gemm<<<ggrid(BM2, Ii, 1), 256, SMEM_BYTES>>>(ctxh, ctxl, wk2h, wk2l, nullptr, nullptr,
        nullptr, kh, kl, BM2, Ii, DCc, DCc, DCc, Ii, 0,0,0,0,0,0, 1, 1.f);
    mma_gemm<<<ggrid(BM2, Ii, 1), 256, SMEM_BYTES>>>(ctxh, ctxl, wv2h, wv2l, nullptr, nullptr,
        v, nullptr, nullptr, BM2, Ii, DCc, DCc, DCc, Ii, 0,0,0,0,0,0, 1, 1.f);

    head_tsplit_kernel<<<dim3((MctxP+31)/32, 2, BHh), tb>>>(v, vth, vtl, Mctx, MctxP);

    // sim2 = Q2 K2^T (q pre-scaled)
    mma_gemm<<<ggrid(Ntok, Mctx, BHh), 256, SMEM_BYTES>>>(qh, ql, kh, kl, nullptr, nullptr,
        sim, nullptr, nullptr, Ntok, Mctx, DHd, Ii, Ii, MctxP,
        (long long)Ntok*Ii, 64, (long long)Mctx*Ii, 64,
        (long long)Hh*Ntok*MctxP, (long long)Ntok*MctxP, Hh, 1.f);

    softmax_split_kernel<<<BHh*Ntok, 256>>>(sim, Ph, Pl, Mctx, MctxP, MctxP);

    // att = P2 @ V2
    mma_gemm<<<ggrid(Ntok, DHd, BHh), 256, SMEM_BYTES>>>(Ph, Pl, vth, vtl, nullptr, nullptr,
        nullptr, atth, attl, Ntok, DHd, MctxP, MctxP, MctxP, Ii,
        (long long)Hh*Ntok*MctxP, (long long)Ntok*MctxP,
        (long long)Hh*DHd*MctxP, (long long)DHd*MctxP,
        (long long)Ntok*Ii, 64, Hh, 1.f);

    // x2 = att @ Wo2 + bo2 + x1
    mma_gemm<<<ggrid(BN, Dm, 1), 256, SMEM_BYTES>>>(atth, attl, wo2h, wo2l, bo2, x1,
        x2, nullptr, nullptr, BN, Dm, Ii, Ii, Ii, Dm, 0,0,0,0,0,0, 1, 1.f);

    // ================= block 3: GEGLU FF =================
    ln_split_kernel<<<BN, 256>>>(x2, ln3_g, ln3_b, lnh, lnl);

    mma_gemm<<<ggrid(BN, 2*FFd, 1), 256, SMEM_BYTES>>>(lnh, lnl, wf1h, wf1l, bff1, nullptr,
        hg, nullptr, nullptr, BN, 2*FFd, Dm, Dm, Dm, 2*FFd, 0,0,0,0,0,0, 1, 1.f);

    geglu_split_kernel<<<(int)(((long long)BN*FFd + 255)/256), 256>>>(hg, ffh, ffl);

    mma_gemm<<<ggrid(BN, Dm, 1), 256, SMEM_BYTES>>>(ffh, ffl, wf2h, wf2l, bff2, x2,
        out, nullptr, nullptr, BN, Dm, FFd, FFd, FFd, Dm, 0,0,0,0,0,0, 1, 1.f);
}

// round 5
// speedup vs baseline: 4.9210x; 1.3113x over previous
#include <cuda_runtime.h>
#include <cuda_fp16.h>
#include <math.h>
#include <stdint.h>

// ---------------------------------------------------------------------------
// Problem constants
// ---------------------------------------------------------------------------
#define Bsz   2
#define Ntok  2048
#define Dm    1024
#define Hh    16
#define DHd   64
#define Ii    1024
#define DCc   768
#define Mctx  77
#define MctxP 80
#define FFd   4096
#define BN    (Bsz*Ntok)
#define BM2   (Bsz*Mctx)
#define BHh   (Bsz*Hh)
#define SCALE 0.125f

// ---------------------------------------------------------------------------
// Device scratch
// ---------------------------------------------------------------------------
#define DEVARR(name, type, count) __device__ __align__(16) type name[(size_t)(count)]

DEVARR(g_lnh,  half, BN*Dm);   DEVARR(g_lnl,  half, BN*Dm);
DEVARR(g_qh,   half, BN*Ii);   DEVARR(g_ql,   half, BN*Ii);
DEVARR(g_kh,   half, BN*Ii);
DEVARR(g_v,    float, BN*Ii);
DEVARR(g_vth,  half, BHh*DHd*Ntok);
DEVARR(g_sim,  float, (size_t)BHh*Ntok*MctxP);            // cross-attn only
DEVARR(g_Ph,   half, (size_t)BHh*Ntok*MctxP); DEVARR(g_Pl, half, (size_t)BHh*Ntok*MctxP);
DEVARR(g_atth, half, BN*Ii);   DEVARR(g_attl, half, BN*Ii);
DEVARR(g_x1,   float, BN*Dm);  DEVARR(g_x2,   float, BN*Dm);
DEVARR(g_ctxh, half, BM2*DCc); DEVARR(g_ctxl, half, BM2*DCc);
DEVARR(g_hg,   float, (size_t)BN*2*FFd);
DEVARR(g_ffh,  half, (size_t)BN*FFd); DEVARR(g_ffl, half, (size_t)BN*FFd);
// transposed weights [N x K], hi only (B-side lo dropped: 2-pass scheme)
DEVARR(g_wq1h, half, Dm*Ii);
DEVARR(g_wk1h, half, Dm*Ii);
DEVARR(g_wv1h, half, Dm*Ii);
DEVARR(g_wo1h, half, Dm*Ii);
DEVARR(g_wq2h, half, Dm*Ii);
DEVARR(g_wk2h, half, DCc*Ii);
DEVARR(g_wv2h, half, DCc*Ii);
DEVARR(g_wo2h, half, Dm*Ii);
DEVARR(g_wf1h, half, (size_t)Dm*2*FFd);
DEVARR(g_wf2h, half, (size_t)FFd*Dm);

// ---------------------------------------------------------------------------
// Helpers
// ---------------------------------------------------------------------------
__device__ __forceinline__ uint32_t smem_u32(const void* p) {
    uint32_t a;
    asm("{ .reg .u64 t; cvta.to.shared.u64 t, %1; cvt.u32.u64 %0, t; }" : "=r"(a) : "l"(p));
    return a;
}
__device__ __forceinline__ void split2(float x, half& h, half& l) {
    h = __float2half_rn(x);
    l = __float2half_rn(x - __half2float(h));
}

#define LDSM4(r0, r1, r2, r3, addr) \
    asm volatile("ldmatrix.sync.aligned.m8n8.x4.shared.b16 {%0,%1,%2,%3}, [%4];" \
        : "=r"(r0), "=r"(r1), "=r"(r2), "=r"(r3) : "r"(addr))

#define MMA16816(c, a, b0, b1) \
    asm volatile("mma.sync.aligned.m16n8k16.row.col.f32.f16.f16.f32 " \
        "{%0,%1,%2,%3}, {%4,%5,%6,%7}, {%8,%9}, {%0,%1,%2,%3};" \
        : "+f"((c)[0]), "+f"((c)[1]), "+f"((c)[2]), "+f"((c)[3]) \
        : "r"((a)[0]), "r"((a)[1]), "r"((a)[2]), "r"((a)[3]), "r"(b0), "r"(b1))

#define CP_ASYNC16(dst, src) \
    asm volatile("cp.async.cg.shared.global [%0], [%1], 16;" :: "r"(dst), "l"(src) : "memory")
#define CP_COMMIT() asm volatile("cp.async.commit_group;" ::: "memory")

// ---------------------------------------------------------------------------
// mma.sync 2-pass split GEMM: C = alpha * (Ah+Al) @ Bh^T (+bias)(+resid)
// A split [M x K] (lda), B hi-only [N x K] (ldb).
// Block tile 128x128, BK=32, 8 warps, cp.async double buffer. 3 tiles/stage.
// ---------------------------------------------------------------------------
#define PITCH   40
#define TILE_H  (128*PITCH)          // 5120 halves
#define STAGE_H (3*TILE_H)
#define SMEM_BYTES (2*STAGE_H*2)     // 61440 B

__global__ void __launch_bounds__(256) mma_gemm(
    const half* __restrict__ Ah_, const half* __restrict__ Al_,
    const half* __restrict__ Bh_,
    const float* __restrict__ bias, const float* __restrict__ resid,
    float* __restrict__ C, half* __restrict__ Ch, half* __restrict__ Cl,
    int M, int N, int K, int lda, int ldb, int ldc,
    long long aO, long long aI, long long bO, long long bI,
    long long cO, long long cI, int nInner, float alpha)
{
    extern __shared__ half sm[];
    uint32_t smBase = smem_u32(sm);
    int tid = threadIdx.x, lane = tid & 31, wid = tid >> 5;
    int warpM = wid >> 1, warpN = wid & 1;

    int z = blockIdx.z, zo = z / nInner, zi = z % nInner;
    const half* Ahp = Ah_ + (long long)zo * aO + (long long)zi * aI;
    const half* Alp = Al_ + (long long)zo * aO + (long long)zi * aI;
    const half* Bhp = Bh_ + (long long)zo * bO + (long long)zi * bI;
    long long offC = (long long)zo * cO + (long long)zi * cI;

    int rowBase = blockIdx.y * 128, colBase = blockIdx.x * 128;

    float acc[2][8][4];
    #pragma unroll
    for (int i = 0; i < 2; i++)
        #pragma unroll
        for (int j = 0; j < 8; j++)
            #pragma unroll
            for (int e = 0; e < 4; e++) acc[i][j][e] = 0.f;

    int nc = (K + 31) >> 5;

    // 3 tiles x 512 16B-segments = 1536 cp.asyncs per stage
    auto load_stage = [&](int c, int s) {
        int k0 = c << 5;
        #pragma unroll
        for (int i = 0; i < 6; i++) {
            int seg  = tid + (i << 8);          // 0..1535
            int tile = seg >> 9;                // 0:Ah 1:Al 2:Bh
            int w    = seg & 511;
            int row  = w >> 2;
            int cs   = (w & 3) << 3;
            bool isA = tile < 2;
            const half* base = (tile == 0) ? Ahp : (tile == 1) ? Alp : Bhp;
            int ld  = isA ? lda : ldb;
            int gr  = (isA ? rowBase : colBase) + row;
            int gk  = k0 + cs;
            bool ok = (gr < (isA ? M : N)) && (gk + 8 <= K);
            const half* src = ok ? (base + (size_t)gr * ld + gk) : base;
            uint32_t dst = smBase + (uint32_t)(((s * 3 + tile) * TILE_H + row * PITCH + cs) * 2);
            uint32_t sz = ok ? 16u : 0u;
            asm volatile("cp.async.cg.shared.global [%0], [%1], 16, %2;"
                         :: "r"(dst), "l"(src), "r"(sz) : "memory");
        }
    };

    int aRow = (lane & 7) + ((lane >> 3) & 1) * 8;
    int aCg  = (lane >> 4) * 8;
    int bRow = (lane & 7) + (lane >> 4) * 8;
    int bCg  = ((lane >> 3) & 1) * 8;

    auto compute_stage = [&](int s) {
        uint32_t sBase = smBase + (uint32_t)(s * STAGE_H * 2);
        #pragma unroll
        for (int ks = 0; ks < 2; ks++) {
            uint32_t ah[2][4], al[2][4];
            #pragma unroll
            for (int mm = 0; mm < 2; mm++) {
                uint32_t addr = sBase + (uint32_t)(((warpM * 32 + mm * 16 + aRow) * PITCH + ks * 16 + aCg) * 2);
                LDSM4(ah[mm][0], ah[mm][1], ah[mm][2], ah[mm][3], addr);
                LDSM4(al[mm][0], al[mm][1], al[mm][2], al[mm][3], addr + TILE_H * 2);
            }
            #pragma unroll
            for (int nn = 0; nn < 4; nn++) {
                uint32_t baddr = sBase + (uint32_t)((2 * TILE_H + (warpN * 64 + nn * 16 + bRow) * PITCH + ks * 16 + bCg) * 2);
                uint32_t bh[4];
                LDSM4(bh[0], bh[1], bh[2], bh[3], baddr);
                #pragma unroll
                for (int mm = 0; mm < 2; mm++) {
                    MMA16816(acc[mm][2 * nn],     ah[mm], bh[0], bh[1]);
                    MMA16816(acc[mm][2 * nn + 1], ah[mm], bh[2], bh[3]);
                    MMA16816(acc[mm][2 * nn],     al[mm], bh[0], bh[1]);
                    MMA16816(acc[mm][2 * nn + 1], al[mm], bh[2], bh[3]);
                }
            }
        }
    };

    load_stage(0, 0);
    CP_COMMIT();
    for (int c = 0; c < nc; c++) {
        if (c + 1 < nc) load_stage(c + 1, (c + 1) & 1);
        CP_COMMIT();
        asm volatile("cp.async.wait_group 1;" ::: "memory");
        __syncthreads();
        compute_stage(c & 1);
        __syncthreads();
    }

    #pragma unroll
    for (int mm = 0; mm < 2; mm++) {
        #pragma unroll
        for (int nf = 0; nf < 8; nf++) {
            int r  = rowBase + warpM * 32 + mm * 16 + (lane >> 2);
            int cc = colBase + warpN * 64 + nf * 8 + (lane & 3) * 2;
            #pragma unroll
            for (int e = 0; e < 4; e++) {
                int rr = r + (e >> 1) * 8;
                int gc = cc + (e & 1);
                if (rr < M && gc < N) {
                    float v = acc[mm][nf][e] * alpha;
                    if (bias) v += bias[gc];
                    size_t idx = (size_t)offC + (size_t)rr * ldc + gc;
                    if (resid) v += resid[idx];
                    if (C) C[idx] = v;
                    if (Ch) {
                        half h, l; split2(v, h, l);
                        Ch[idx] = h;
                        if (Cl) Cl[idx] = l;
                    }
                }
            }
        }
    }
}

// ---------------------------------------------------------------------------
// Fused flash self-attention (2-pass QK: (Qh+Ql)·Kh; PV: (Ph+Pl)·Vh).
// grid (Ntok/128, BHh), 256 threads, warp = 16 q rows.
// ---------------------------------------------------------------------------
#define FA_PITCH  72
#define FA_VPITCH 136
#define FA_QT     (128*FA_PITCH)  // 9216 halves
#define FA_VT     (64*FA_VPITCH)  // 8704 halves
#define FA_KBASE  (2*FA_QT)
#define FA_VBASE  (4*FA_QT)
#define FA_SMEM_H (4*FA_QT + 2*FA_VT)
#define FA_SMEM_BYTES (FA_SMEM_H*2)   // 108544

__global__ void __launch_bounds__(256) flash_attn(
    const half* __restrict__ qh, const half* __restrict__ ql,
    const half* __restrict__ kh, const half* __restrict__ vth,
    half* __restrict__ atth, half* __restrict__ attl)
{
    extern __shared__ half sm[];
    uint32_t smBase = smem_u32(sm);
    int tid = threadIdx.x, lane = tid & 31, wid = tid >> 5;

    int bh = blockIdx.y;
    int b = bh >> 4, h = bh & 15;
    int q0 = blockIdx.x * 128;
    int qg0 = b * Ntok + q0;
    int kg0 = b * Ntok;
    int hcol = h * 64;
    size_t vbase = (size_t)bh * 64 * Ntok;

    auto ldQ = [&]() {
        #pragma unroll
        for (int i = 0; i < 8; i++) {
            int seg = tid + (i << 8);           // 0..2047
            int hl = seg >> 10;
            int w = seg & 1023;
            int row = w >> 3;
            int cs = (w & 7) << 3;
            const half* src = (hl ? ql : qh) + (size_t)(qg0 + row) * Ii + hcol + cs;
            uint32_t dst = smBase + (uint32_t)((hl * FA_QT + row * FA_PITCH + cs) * 2);
            CP_ASYNC16(dst, src);
        }
    };
    auto ldKV = [&](int chunk, int s) {
        int key0 = chunk << 7;
        #pragma unroll
        for (int i = 0; i < 8; i++) {
            int seg = tid + (i << 8);           // 0..2047
            int t = seg >> 10;                  // 0 Kh, 1 Vh
            int w = seg & 1023;
            if (t == 0) {
                int row = w >> 3;
                int cs = (w & 7) << 3;
                const half* src = kh + (size_t)(kg0 + key0 + row) * Ii + hcol + cs;
                uint32_t dst = smBase + (uint32_t)((FA_KBASE + s * FA_QT + row * FA_PITCH + cs) * 2);
                CP_ASYNC16(dst, src);
            } else {
                int row = w >> 4;
                int cs = (w & 15) << 3;
                const half* src = vth + vbase + (size_t)row * Ntok + key0 + cs;
                uint32_t dst = smBase + (uint32_t)((FA_VBASE + s * FA_VT + row * FA_VPITCH + cs) * 2);
                CP_ASYNC16(dst, src);
            }
        }
    };

    int aRow = (lane & 7) + ((lane >> 3) & 1) * 8;
    int aCg  = (lane >> 4) * 8;
    int bRow = (lane & 7) + (lane >> 4) * 8;
    int bCg  = ((lane >> 3) & 1) * 8;

    float O[8][4];
    #pragma unroll
    for (int i = 0; i < 8; i++)
        #pragma unroll
        for (int e = 0; e < 4; e++) O[i][e] = 0.f;
    float M0 = -1e30f, M1 = -1e30f, L0 = 0.f, L1 = 0.f;

    ldQ(); ldKV(0, 0);
    CP_COMMIT();
    ldKV(1, 1);
    CP_COMMIT();

    for (int c = 0; c < 16; c++) {
        if (c < 15) asm volatile("cp.async.wait_group 1;" ::: "memory");
        else        asm volatile("cp.async.wait_group 0;" ::: "memory");
        __syncthreads();

        int s = c & 1;
        // ---- S = Q K^T (pre-scaled), 16x128 per warp ----
        float S[16][4];
        #pragma unroll
        for (int i = 0; i < 16; i++)
            #pragma unroll
            for (int e = 0; e < 4; e++) S[i][e] = 0.f;

        uint32_t kTile = smBase + (uint32_t)((FA_KBASE + s * FA_QT) * 2);
        #pragma unroll
        for (int ks = 0; ks < 4; ks++) {
            uint32_t aH[4], aL[4];
            uint32_t addrA = smBase + (uint32_t)(((wid * 16 + aRow) * FA_PITCH + ks * 16 + aCg) * 2);
            LDSM4(aH[0], aH[1], aH[2], aH[3], addrA);
            LDSM4(aL[0], aL[1], aL[2], aL[3], addrA + FA_QT * 2);
            #pragma unroll
            for (int nn = 0; nn < 8; nn++) {
                uint32_t addrB = kTile + (uint32_t)(((nn * 16 + bRow) * FA_PITCH + ks * 16 + bCg) * 2);
                uint32_t bH[4];
                LDSM4(bH[0], bH[1], bH[2], bH[3], addrB);
                MMA16816(S[2 * nn],     aH, bH[0], bH[1]);
                MMA16816(S[2 * nn + 1], aH, bH[2], bH[3]);
                MMA16816(S[2 * nn],     aL, bH[0], bH[1]);
                MMA16816(S[2 * nn + 1], aL, bH[2], bH[3]);
            }
        }

        // ---- online softmax ----
        float cm0 = -1e30f, cm1 = -1e30f;
        #pragma unroll
        for (int i = 0; i < 16; i++) {
            cm0 = fmaxf(cm0, fmaxf(S[i][0], S[i][1]));
            cm1 = fmaxf(cm1, fmaxf(S[i][2], S[i][3]));
        }
        #pragma unroll
        for (int o = 1; o <= 2; o <<= 1) {
            cm0 = fmaxf(cm0, __shfl_xor_sync(0xffffffffu, cm0, o));
            cm1 = fmaxf(cm1, __shfl_xor_sync(0xffffffffu, cm1, o));
        }
        float nM0 = fmaxf(M0, cm0), nM1 = fmaxf(M1, cm1);
        float f0 = __expf(M0 - nM0), f1 = __expf(M1 - nM1);
        M0 = nM0; M1 = nM1;
        #pragma unroll
        for (int i = 0; i < 8; i++) {
            O[i][0] *= f0; O[i][1] *= f0; O[i][2] *= f1; O[i][3] *= f1;
        }
        float l0 = 0.f, l1 = 0.f;
        #pragma unroll
        for (int i = 0; i < 16; i++) {
            S[i][0] = __expf(S[i][0] - nM0);
            S[i][1] = __expf(S[i][1] - nM0);
            S[i][2] = __expf(S[i][2] - nM1);
            S[i][3] = __expf(S[i][3] - nM1);
            l0 += S[i][0] + S[i][1];
            l1 += S[i][2] + S[i][3];
        }
        #pragma unroll
        for (int o = 1; o <= 2; o <<= 1) {
            l0 += __shfl_xor_sync(0xffffffffu, l0, o);
            l1 += __shfl_xor_sync(0xffffffffu, l1, o);
        }
        L0 = L0 * f0 + l0;
        L1 = L1 * f1 + l1;

        // ---- O += P @ V (P split in registers, V hi-only) ----
        uint32_t vTile = smBase + (uint32_t)((FA_VBASE + s * FA_VT) * 2);
        #pragma unroll
        for (int kk = 0; kk < 8; kk++) {
            uint32_t PhF[4], PlF[4];
            #pragma unroll
            for (int u = 0; u < 2; u++) {
                int t = 2 * kk + u;
                half2 h01 = __floats2half2_rn(S[t][0], S[t][1]);
                half2 h23 = __floats2half2_rn(S[t][2], S[t][3]);
                float r0a = S[t][0] - __low2float(h01);
                float r0b = S[t][1] - __high2float(h01);
                float r1a = S[t][2] - __low2float(h23);
                float r1b = S[t][3] - __high2float(h23);
                half2 lo01 = __floats2half2_rn(r0a, r0b);
                half2 lo23 = __floats2half2_rn(r1a, r1b);
                PhF[2 * u]     = *reinterpret_cast<uint32_t*>(&h01);
                PhF[2 * u + 1] = *reinterpret_cast<uint32_t*>(&h23);
                PlF[2 * u]     = *reinterpret_cast<uint32_t*>(&lo01);
                PlF[2 * u + 1] = *reinterpret_cast<uint32_t*>(&lo23);
            }
            #pragma unroll
            for (int nn = 0; nn < 4; nn++) {
                uint32_t addrV = vTile + (uint32_t)(((nn * 16 + bRow) * FA_VPITCH + kk * 16 + bCg) * 2);
                uint32_t vH[4];
                LDSM4(vH[0], vH[1], vH[2], vH[3], addrV);
                MMA16816(O[2 * nn],     PhF, vH[0], vH[1]);
                MMA16816(O[2 * nn + 1], PhF, vH[2], vH[3]);
                MMA16816(O[2 * nn],     PlF, vH[0], vH[1]);
                MMA16816(O[2 * nn + 1], PlF, vH[2], vH[3]);
            }
        }

        __syncthreads();
        if (c + 2 < 16) { ldKV(c + 2, s); CP_COMMIT(); }
    }

    // ---- finalize ----
    float inv0 = 1.f / L0, inv1 = 1.f / L1;
    int r0 = qg0 + wid * 16 + (lane >> 2);
    int r1 = r0 + 8;
    #pragma unroll
    for (int nf = 0; nf < 8; nf++) {
        int d0 = nf * 8 + (lane & 3) * 2;
        float v00 = O[nf][0] * inv0, v01 = O[nf][1] * inv0;
        float v10 = O[nf][2] * inv1, v11 = O[nf][3] * inv1;
        half h0, l0h, h1, l1h, h2a, l2, h3, l3;
        split2(v00, h0, l0h); split2(v01, h1, l1h);
        split2(v10, h2a, l2); split2(v11, h3, l3);
        *reinterpret_cast<half2*>(atth + (size_t)r0 * Ii + hcol + d0) = __halves2half2(h0, h1);
        *reinterpret_cast<half2*>(attl + (size_t)r0 * Ii + hcol + d0) = __halves2half2(l0h, l1h);
        *reinterpret_cast<half2*>(atth + (size_t)r1 * Ii + hcol + d0) = __halves2half2(h2a, h3);
        *reinterpret_cast<half2*>(attl + (size_t)r1 * Ii + hcol + d0) = __halves2half2(l2, l3);
    }
}

// ---------------------------------------------------------------------------
// LayerNorm -> split fp16
// ---------------------------------------------------------------------------
__global__ __launch_bounds__(256) void ln_split_kernel(
    const float* __restrict__ x, const float* __restrict__ g, const float* __restrict__ b,
    half* __restrict__ oh, half* __restrict__ ol)
{
    size_t row = blockIdx.x;
    const float* xr = x + row * Dm;
    __shared__ float red[256];
    int t = threadIdx.x;
    float v[4];
    float s = 0.f;
    #pragma unroll
    for (int j = 0; j < 4; j++) { v[j] = xr[t + j * 256]; s += v[j]; }
    red[t] = s; __syncthreads();
    for (int o = 128; o > 0; o >>= 1) { if (t < o) red[t] += red[t + o]; __syncthreads(); }
    float mean = red[0] * (1.f / Dm);
    __syncthreads();
    float s2 = 0.f;
    #pragma unroll
    for (int j = 0; j < 4; j++) { float d = v[j] - mean; s2 += d * d; }
    red[t] = s2; __syncthreads();
    for (int o = 128; o > 0; o >>= 1) { if (t < o) red[t] += red[t + o]; __syncthreads(); }
    float inv = rsqrtf(red[0] * (1.f / Dm) + 1e-5f);
    #pragma unroll
    for (int j = 0; j < 4; j++) {
        int i = t + j * 256;
        float val = (v[j] - mean) * inv * g[i] + b[i];
        half h, l; split2(val, h, l);
        oh[row * Dm + i] = h; ol[row * Dm + i] = l;
    }
}

// ---------------------------------------------------------------------------
// Softmax -> split fp16 (cross-attn, 77 cols padded to 80)
// ---------------------------------------------------------------------------
__global__ __launch_bounds__(256) void softmax_split_kernel(
    const float* __restrict__ s, half* __restrict__ ph, half* __restrict__ pl,
    int cols, int ldin, int ldout)
{
    size_t row = blockIdx.x;
    const float* r = s + row * (size_t)ldin;
    __shared__ float red[256];
    int t = threadIdx.x;
    float v = (t < cols) ? r[t] : -INFINITY;
    red[t] = v; __syncthreads();
    for (int o = 128; o > 0; o >>= 1) { if (t < o) red[t] = fmaxf(red[t], red[t + o]); __syncthreads(); }
    float m = red[0]; __syncthreads();
    float e = (t < cols) ? __expf(v - m) : 0.f;
    red[t] = e; __syncthreads();
    for (int o = 128; o > 0; o >>= 1) { if (t < o) red[t] += red[t + o]; __syncthreads(); }
    float inv = 1.f / red[0];
    if (t < ldout) {
        half h, l; split2(e * inv, h, l);
        ph[row * (size_t)ldout + t] = h;
        pl[row * (size_t)ldout + t] = l;
    }
}

// ---------------------------------------------------------------------------
// GEGLU -> split fp16
// ---------------------------------------------------------------------------
__global__ __launch_bounds__(256) void geglu_split_kernel(
    const float* __restrict__ hg, half* __restrict__ oh, half* __restrict__ ol)
{
    size_t idx = (size_t)blockIdx.x * 256 + threadIdx.x;
    if (idx >= (size_t)BN * FFd) return;
    size_t r = idx / FFd; int c = (int)(idx % FFd);
    float h = hg[r * (2 * FFd) + c];
    float g = hg[r * (2 * FFd) + FFd + c];
    float gl = 0.5f * g * (1.f + erff(g * 0.70710678118654752440f));
    half hh, ll; split2(h * gl, hh, ll);
    oh[idx] = hh; ol[idx] = ll;
}

// ---------------------------------------------------------------------------
// Plain split
// ---------------------------------------------------------------------------
__global__ __launch_bounds__(256) void split_kernel(
    const float* __restrict__ src, half* __restrict__ dh, half* __restrict__ dl, long long n)
{
    long long i = (long long)blockIdx.x * 256 + threadIdx.x;
    if (i >= n) return;
    half h, l; split2(src[i], h, l);
    dh[i] = h; dl[i] = l;
}

// ---------------------------------------------------------------------------
// Transpose (+optional split): src [R x C] fp32 -> dst [C x R] fp16 (hi, opt lo)
// ---------------------------------------------------------------------------
__global__ __launch_bounds__(1024) void tsplit_kernel(
    const float* __restrict__ src, half* __restrict__ dh, half* __restrict__ dl, int R, int C)
{
    __shared__ float tile[32][33];
    int c0 = blockIdx.x * 32, r0 = blockIdx.y * 32;
    int tx = threadIdx.x, ty = threadIdx.y;
    int r = r0 + ty, c = c0 + tx;
    tile[ty][tx] = (r < R && c < C) ? src[(size_t)r * C + c] : 0.f;
    __syncthreads();
    int rr = r0 + tx, cc = c0 + ty;
    if (rr < R && cc < C) {
        half h, l; split2(tile[tx][ty], h, l);
        dh[(size_t)cc * R + rr] = h;
        if (dl) dl[(size_t)cc * R + rr] = l;
    }
}

// ---------------------------------------------------------------------------
// Per-head transpose of V (hi only)
// ---------------------------------------------------------------------------
__global__ __launch_bounds__(1024) void head_tsplit_kernel(
    const float* __restrict__ src, half* __restrict__ dh,
    int T, int Tpad)
{
    __shared__ float tile[32][33];
    int zh = blockIdx.z;
    int b = zh >> 4, h = zh & 15;
    int tx = threadIdx.x, ty = threadIdx.y;
    int t0 = blockIdx.x * 32, d0 = blockIdx.y * 32;
    int t = t0 + ty, d = d0 + tx;
    tile[ty][tx] = (t < T) ? src[((size_t)b * T + t) * 1024 + h * 64 + d] : 0.f;
    __syncthreads();
    int dd = d0 + ty, tt = t0 + tx;
    if (tt < Tpad) {
        size_t base = (size_t)zh * 64 * Tpad + (size_t)dd * Tpad + tt;
        dh[base] = __float2half_rn(tile[tx][ty]);
    }
}

// ---------------------------------------------------------------------------
// Orchestration
// ---------------------------------------------------------------------------
static inline dim3 ggrid(int M, int N, int z) { return dim3((N + 127) / 128, (M + 127) / 128, z); }

#define SYM(p, s) cudaGetSymbolAddress((void**)&p, s)

extern "C" void kernel_launch(void* const* d_in, const int* in_sizes, int n_in,
                              void* d_out, int out_size)
{
    const float* x     = (const float*)d_in[0];
    const float* ctx   = (const float*)d_in[1];
    const float* ln1_g = (const float*)d_in[2];
    const float* ln1_b = (const float*)d_in[3];
    const float* ln2_g = (const float*)d_in[4];
    const float* ln2_b = (const float*)d_in[5];
    const float* ln3_g = (const float*)d_in[6];
    const float* ln3_b = (const float*)d_in[7];
    const float* Wq1   = (const float*)d_in[8];
    const float* Wk1   = (const float*)d_in[9];
    const float* Wv1   = (const float*)d_in[10];
    const float* Wo1   = (const float*)d_in[11];
    const float* bo1   = (const float*)d_in[12];
    const float* Wq2   = (const float*)d_in[13];
    const float* Wk2   = (const float*)d_in[14];
    const float* Wv2   = (const float*)d_in[15];
    const float* Wo2   = (const float*)d_in[16];
    const float* bo2   = (const float*)d_in[17];
    const float* Wff1  = (const float*)d_in[18];
    const float* bff1  = (const float*)d_in[19];
    const float* Wff2  = (const float*)d_in[20];
    const float* bff2  = (const float*)d_in[21];
    float* out = (float*)d_out;

    half *lnh,*lnl,*qh,*ql,*kh,*vth,*Ph,*Pl,*atth,*attl,*ctxh,*ctxl,*ffh,*ffl;
    half *wq1h,*wk1h,*wv1h,*wo1h,*wq2h,*wk2h,*wv2h,*wo2h,*wf1h,*wf2h;
    float *v,*sim,*x1,*x2,*hg;
    SYM(lnh,g_lnh); SYM(lnl,g_lnl); SYM(qh,g_qh); SYM(ql,g_ql); SYM(kh,g_kh);
    SYM(v,g_v); SYM(vth,g_vth); SYM(sim,g_sim); SYM(Ph,g_Ph); SYM(Pl,g_Pl);
    SYM(atth,g_atth); SYM(attl,g_attl); SYM(x1,g_x1); SYM(x2,g_x2);
    SYM(ctxh,g_ctxh); SYM(ctxl,g_ctxl); SYM(hg,g_hg); SYM(ffh,g_ffh); SYM(ffl,g_ffl);
    SYM(wq1h,g_wq1h); SYM(wk1h,g_wk1h); SYM(wv1h,g_wv1h); SYM(wo1h,g_wo1h);
    SYM(wq2h,g_wq2h); SYM(wk2h,g_wk2h); SYM(wv2h,g_wv2h); SYM(wo2h,g_wo2h);
    SYM(wf1h,g_wf1h); SYM(wf2h,g_wf2h);

    cudaFuncSetAttribute(mma_gemm, cudaFuncAttributeMaxDynamicSharedMemorySize, SMEM_BYTES);
    cudaFuncSetAttribute(flash_attn, cudaFuncAttributeMaxDynamicSharedMemorySize, FA_SMEM_BYTES);

    dim3 tb(32, 32);
    // ---- weight transposes (hi only) ----
    tsplit_kernel<<<dim3(Ii/32, Dm/32), tb>>>(Wq1, wq1h, nullptr, Dm, Ii);
    tsplit_kernel<<<dim3(Ii/32, Dm/32), tb>>>(Wk1, wk1h, nullptr, Dm, Ii);
    tsplit_kernel<<<dim3(Ii/32, Dm/32), tb>>>(Wv1, wv1h, nullptr, Dm, Ii);
    tsplit_kernel<<<dim3(Dm/32, Ii/32), tb>>>(Wo1, wo1h, nullptr, Ii, Dm);
    tsplit_kernel<<<dim3(Ii/32, Dm/32), tb>>>(Wq2, wq2h, nullptr, Dm, Ii);
    tsplit_kernel<<<dim3(Ii/32, DCc/32), tb>>>(Wk2, wk2h, nullptr, DCc, Ii);
    tsplit_kernel<<<dim3(Ii/32, DCc/32), tb>>>(Wv2, wv2h, nullptr, DCc, Ii);
    tsplit_kernel<<<dim3(Dm/32, Ii/32), tb>>>(Wo2, wo2h, nullptr, Ii, Dm);
    tsplit_kernel<<<dim3((2*FFd)/32, Dm/32), tb>>>(Wff1, wf1h, nullptr, Dm, 2*FFd);
    tsplit_kernel<<<dim3(Dm/32, FFd/32), tb>>>(Wff2, wf2h, nullptr, FFd, Dm);
    split_kernel<<<(BM2*DCc + 255)/256, 256>>>(ctx, ctxh, ctxl, (long long)BM2*DCc);

    // ================= block 1: self-attention =================
    ln_split_kernel<<<BN, 256>>>(x, ln1_g, ln1_b, lnh, lnl);

    // q pre-scaled by SCALE
    mma_gemm<<<ggrid(BN, Ii, 1), 256, SMEM_BYTES>>>(lnh, lnl, wq1h, nullptr, nullptr,
        nullptr, qh, ql, BN, Ii, Dm, Dm, Dm, Ii, 0,0,0,0,0,0, 1, SCALE);
    mma_gemm<<<ggrid(BN, Ii, 1), 256, SMEM_BYTES>>>(lnh, lnl, wk1h, nullptr, nullptr,
        nullptr, kh, nullptr, BN, Ii, Dm, Dm, Dm, Ii, 0,0,0,0,0,0, 1, 1.f);
    mma_gemm<<<ggrid(BN, Ii, 1), 256, SMEM_BYTES>>>(lnh, lnl, wv1h, nullptr, nullptr,
        v, nullptr, nullptr, BN, Ii, Dm, Dm, Dm, Ii, 0,0,0,0,0,0, 1, 1.f);

    head_tsplit_kernel<<<dim3(Ntok/32, 2, BHh), tb>>>(v, vth, Ntok, Ntok);

    // fused flash attention -> atth/attl
    flash_attn<<<dim3(Ntok/128, BHh), 256, FA_SMEM_BYTES>>>(qh, ql, kh, vth, atth, attl);

    // x1 = att @ Wo1 + bo1 + x
    mma_gemm<<<ggrid(BN, Dm, 1), 256, SMEM_BYTES>>>(atth, attl, wo1h, bo1, x,
        x1, nullptr, nullptr, BN, Dm, Ii, Ii, Ii, Dm, 0,0,0,0,0,0, 1, 1.f);

    // ================= block 2: cross-attention =================
    ln_split_kernel<<<BN, 256>>>(x1, ln2_g, ln2_b, lnh, lnl);

    mma_gemm<<<ggrid(BN, Ii, 1), 256, SMEM_BYTES>>>(lnh, lnl, wq2h, nullptr, nullptr,
        nullptr, qh, ql, BN, Ii, Dm, Dm, Dm, Ii, 0,0,0,0,0,0, 1, SCALE);
    mma_gemm<<<ggrid(BM2, Ii, 1), 256, SMEM_BYTES>>>(ctxh, ctxl, wk2h, nullptr, nullptr,
        nullptr, kh, nullptr, BM2, Ii, DCc, DCc, DCc, Ii, 0,0,0,0,0,0, 1, 1.f);
    mma_gemm<<<ggrid(BM2, Ii, 1), 256, SMEM_BYTES>>>(ctxh, ctxl, wv2h, nullptr, nullptr,
        v, nullptr, nullptr, BM2, Ii, DCc, DCc, DCc, Ii, 0,0,0,0,0,0, 1, 1.f);

    head_tsplit_kernel<<<dim3((MctxP+31)/32, 2, BHh), tb>>>(v, vth, Mctx, MctxP);

    // sim2 = Q2 K2^T (q pre-scaled)
    mma_gemm<<<ggrid(Ntok, Mctx, BHh), 256, SMEM_BYTES>>>(qh, ql, kh, nullptr, nullptr,
        sim, nullptr, nullptr, Ntok, Mctx, DHd, Ii, Ii, MctxP,
        (long long)Ntok*Ii, 64, (long long)Mctx*Ii, 64,
        (long long)Hh*Ntok*MctxP, (long long)Ntok*MctxP, Hh, 1.f);

    softmax_split_kernel<<<BHh*Ntok, 256>>>(sim, Ph, Pl, Mctx, MctxP, MctxP);

    // att = P2 @ V2
    mma_gemm<<<ggrid(Ntok, DHd, BHh), 256, SMEM_BYTES>>>(Ph, Pl, vth, nullptr, nullptr,
        nullptr, atth, attl, Ntok, DHd, MctxP, MctxP, MctxP, Ii,
        (long long)Hh*Ntok*MctxP, (long long)Ntok*MctxP,
        (long long)Hh*DHd*MctxP, (long long)DHd*MctxP,
        (long long)Ntok*Ii, 64, Hh, 1.f);

    // x2 = att @ Wo2 + bo2 + x1
    mma_gemm<<<ggrid(BN, Dm, 1), 256, SMEM_BYTES>>>(atth, attl, wo2h, bo2, x1,
        x2, nullptr, nullptr, BN, Dm, Ii, Ii, Ii, Dm, 0,0,0,0,0,0, 1, 1.f);

    // ================= block 3: GEGLU FF =================
    ln_split_kernel<<<BN, 256>>>(x2, ln3_g, ln3_b, lnh, lnl);

    mma_gemm<<<ggrid(BN, 2*FFd, 1), 256, SMEM_BYTES>>>(lnh, lnl, wf1h, bff1, nullptr,
        hg, nullptr, nullptr, BN, 2*FFd, Dm, Dm, Dm, 2*FFd, 0,0,0,0,0,0, 1, 1.f);

    geglu_split_kernel<<<(int)(((long long)BN*FFd + 255)/256), 256>>>(hg, ffh, ffl);

    mma_gemm<<<ggrid(BN, Dm, 1), 256, SMEM_BYTES>>>(ffh, ffl, wf2h, bff2, x2,
        out, nullptr, nullptr, BN, Dm, FFd, FFd, FFd, Dm, 0,0,0,0,0,0, 1, 1.f);
}

// round 6
// speedup vs baseline: 7.1312x; 1.4492x over previous
#include <cuda_runtime.h>
#include <cuda_fp16.h>
#include <math.h>
#include <stdint.h>

// ---------------------------------------------------------------------------
// Problem constants
// ---------------------------------------------------------------------------
#define Bsz   2
#define Ntok  2048
#define Dm    1024
#define Hh    16
#define DHd   64
#define Ii    1024
#define DCc   768
#define Mctx  77
#define MctxP 80
#define FFd   4096
#define BN    (Bsz*Ntok)
#define BM2   (Bsz*Mctx)
#define BHh   (Bsz*Hh)
#define SCALE 0.125f

// ---------------------------------------------------------------------------
// Device scratch
// ---------------------------------------------------------------------------
#define DEVARR(name, type, count) __device__ __align__(16) type name[(size_t)(count)]

DEVARR(g_lnh,  half, BN*Dm);
DEVARR(g_qh,   half, BN*Ii);
DEVARR(g_kh,   half, BN*Ii);
DEVARR(g_v,    float, BN*Ii);
DEVARR(g_vth,  half, BHh*DHd*Ntok);
DEVARR(g_sim,  float, (size_t)BHh*Ntok*MctxP);
DEVARR(g_Ph,   half, (size_t)BHh*Ntok*MctxP); DEVARR(g_Pl, half, (size_t)BHh*Ntok*MctxP);
DEVARR(g_atth, half, BN*Ii);
DEVARR(g_x1,   float, BN*Dm);  DEVARR(g_x2,   float, BN*Dm);
DEVARR(g_ctxh, half, BM2*DCc);
DEVARR(g_hg,   float, (size_t)BN*2*FFd);
DEVARR(g_ffh,  half, (size_t)BN*FFd);
// transposed weights [N x K], hi only
DEVARR(g_wq1h, half, Dm*Ii);
DEVARR(g_wk1h, half, Dm*Ii);
DEVARR(g_wv1h, half, Dm*Ii);
DEVARR(g_wo1h, half, Dm*Ii);
DEVARR(g_wq2h, half, Dm*Ii);
DEVARR(g_wk2h, half, DCc*Ii);
DEVARR(g_wv2h, half, DCc*Ii);
DEVARR(g_wo2h, half, Dm*Ii);
DEVARR(g_wf1h, half, (size_t)Dm*2*FFd);
DEVARR(g_wf2h, half, (size_t)FFd*Dm);

// ---------------------------------------------------------------------------
// Helpers
// ---------------------------------------------------------------------------
__device__ __forceinline__ uint32_t smem_u32(const void* p) {
    uint32_t a;
    asm("{ .reg .u64 t; cvta.to.shared.u64 t, %1; cvt.u32.u64 %0, t; }" : "=r"(a) : "l"(p));
    return a;
}
__device__ __forceinline__ void split2(float x, half& h, half& l) {
    h = __float2half_rn(x);
    l = __float2half_rn(x - __half2float(h));
}

#define LDSM4(r0, r1, r2, r3, addr) \
    asm volatile("ldmatrix.sync.aligned.m8n8.x4.shared.b16 {%0,%1,%2,%3}, [%4];" \
        : "=r"(r0), "=r"(r1), "=r"(r2), "=r"(r3) : "r"(addr))

#define MMA16816(c, a, b0, b1) \
    asm volatile("mma.sync.aligned.m16n8k16.row.col.f32.f16.f16.f32 " \
        "{%0,%1,%2,%3}, {%4,%5,%6,%7}, {%8,%9}, {%0,%1,%2,%3};" \
        : "+f"((c)[0]), "+f"((c)[1]), "+f"((c)[2]), "+f"((c)[3]) \
        : "r"((a)[0]), "r"((a)[1]), "r"((a)[2]), "r"((a)[3]), "r"(b0), "r"(b1))

#define CP_ASYNC16(dst, src) \
    asm volatile("cp.async.cg.shared.global [%0], [%1], 16;" :: "r"(dst), "l"(src) : "memory")
#define CP_COMMIT() asm volatile("cp.async.commit_group;" ::: "memory")

// ---------------------------------------------------------------------------
// mma.sync GEMM: C = alpha * A @ Bh^T (+bias)(+resid)
// SPLIT_A=1: A = Ah+Al (2-pass). SPLIT_A=0: A = Ah (1-pass).
// A [M x K] (lda), B hi-only [N x K] (ldb).
// Block tile 128x128, BK=32, 8 warps, cp.async double buffer.
// ---------------------------------------------------------------------------
#define PITCH   40
#define TILE_H  (128*PITCH)          // 5120 halves

template<int SPLIT_A>
__global__ void __launch_bounds__(256) mma_gemm(
    const half* __restrict__ Ah_, const half* __restrict__ Al_,
    const half* __restrict__ Bh_,
    const float* __restrict__ bias, const float* __restrict__ resid,
    float* __restrict__ C, half* __restrict__ Ch,
    int M, int N, int K, int lda, int ldb, int ldc,
    long long aO, long long aI, long long bO, long long bI,
    long long cO, long long cI, int nInner, float alpha)
{
    constexpr int NT = 2 + SPLIT_A;           // tiles per stage
    extern __shared__ half sm[];
    uint32_t smBase = smem_u32(sm);
    int tid = threadIdx.x, lane = tid & 31, wid = tid >> 5;
    int warpM = wid >> 1, warpN = wid & 1;

    int z = blockIdx.z, zo = z / nInner, zi = z % nInner;
    const half* Ahp = Ah_ + (long long)zo * aO + (long long)zi * aI;
    const half* Alp = SPLIT_A ? (Al_ + (long long)zo * aO + (long long)zi * aI) : nullptr;
    const half* Bhp = Bh_ + (long long)zo * bO + (long long)zi * bI;
    long long offC = (long long)zo * cO + (long long)zi * cI;

    int rowBase = blockIdx.y * 128, colBase = blockIdx.x * 128;

    float acc[2][8][4];
    #pragma unroll
    for (int i = 0; i < 2; i++)
        #pragma unroll
        for (int j = 0; j < 8; j++)
            #pragma unroll
            for (int e = 0; e < 4; e++) acc[i][j][e] = 0.f;

    int nc = (K + 31) >> 5;

    auto load_stage = [&](int c, int s) {
        int k0 = c << 5;
        #pragma unroll
        for (int i = 0; i < 2 * NT; i++) {
            int seg  = tid + (i << 8);          // 0 .. NT*512-1
            int tile = seg >> 9;                // 0:Ah [1:Al] last:Bh
            int w    = seg & 511;
            int row  = w >> 2;
            int cs   = (w & 3) << 3;
            bool isA = tile < (NT - 1);
            const half* base = (tile == 0) ? Ahp : (SPLIT_A && tile == 1) ? Alp : Bhp;
            int ld  = isA ? lda : ldb;
            int gr  = (isA ? rowBase : colBase) + row;
            int gk  = k0 + cs;
            bool ok = (gr < (isA ? M : N)) && (gk + 8 <= K);
            const half* src = ok ? (base + (size_t)gr * ld + gk) : base;
            uint32_t dst = smBase + (uint32_t)(((s * NT + tile) * TILE_H + row * PITCH + cs) * 2);
            uint32_t sz = ok ? 16u : 0u;
            asm volatile("cp.async.cg.shared.global [%0], [%1], 16, %2;"
                         :: "r"(dst), "l"(src), "r"(sz) : "memory");
        }
    };

    int aRow = (lane & 7) + ((lane >> 3) & 1) * 8;
    int aCg  = (lane >> 4) * 8;
    int bRow = (lane & 7) + (lane >> 4) * 8;
    int bCg  = ((lane >> 3) & 1) * 8;

    auto compute_stage = [&](int s) {
        uint32_t sBase = smBase + (uint32_t)(s * NT * TILE_H * 2);
        #pragma unroll
        for (int ks = 0; ks < 2; ks++) {
            uint32_t ah[2][4], al[2][4];
            #pragma unroll
            for (int mm = 0; mm < 2; mm++) {
                uint32_t addr = sBase + (uint32_t)(((warpM * 32 + mm * 16 + aRow) * PITCH + ks * 16 + aCg) * 2);
                LDSM4(ah[mm][0], ah[mm][1], ah[mm][2], ah[mm][3], addr);
                if (SPLIT_A) LDSM4(al[mm][0], al[mm][1], al[mm][2], al[mm][3], addr + TILE_H * 2);
            }
            #pragma unroll
            for (int nn = 0; nn < 4; nn++) {
                uint32_t baddr = sBase + (uint32_t)(((NT - 1) * TILE_H + (warpN * 64 + nn * 16 + bRow) * PITCH + ks * 16 + bCg) * 2);
                uint32_t bh[4];
                LDSM4(bh[0], bh[1], bh[2], bh[3], baddr);
                #pragma unroll
                for (int mm = 0; mm < 2; mm++) {
                    MMA16816(acc[mm][2 * nn],     ah[mm], bh[0], bh[1]);
                    MMA16816(acc[mm][2 * nn + 1], ah[mm], bh[2], bh[3]);
                    if (SPLIT_A) {
                        MMA16816(acc[mm][2 * nn],     al[mm], bh[0], bh[1]);
                        MMA16816(acc[mm][2 * nn + 1], al[mm], bh[2], bh[3]);
                    }
                }
            }
        }
    };

    load_stage(0, 0);
    CP_COMMIT();
    for (int c = 0; c < nc; c++) {
        if (c + 1 < nc) load_stage(c + 1, (c + 1) & 1);
        CP_COMMIT();
        asm volatile("cp.async.wait_group 1;" ::: "memory");
        __syncthreads();
        compute_stage(c & 1);
        __syncthreads();
    }

    #pragma unroll
    for (int mm = 0; mm < 2; mm++) {
        #pragma unroll
        for (int nf = 0; nf < 8; nf++) {
            int r  = rowBase + warpM * 32 + mm * 16 + (lane >> 2);
            int cc = colBase + warpN * 64 + nf * 8 + (lane & 3) * 2;
            #pragma unroll
            for (int e = 0; e < 4; e++) {
                int rr = r + (e >> 1) * 8;
                int gc = cc + (e & 1);
                if (rr < M && gc < N) {
                    float v = acc[mm][nf][e] * alpha;
                    if (bias) v += bias[gc];
                    size_t idx = (size_t)offC + (size_t)rr * ldc + gc;
                    if (resid) v += resid[idx];
                    if (C) C[idx] = v;
                    if (Ch) Ch[idx] = __float2half_rn(v);
                }
            }
        }
    }
}

#define SMEM_G1 (2*2*TILE_H*2)   // SPLIT_A=0: 40960 B
#define SMEM_G2 (2*3*TILE_H*2)   // SPLIT_A=1: 61440 B

// ---------------------------------------------------------------------------
// Fused flash self-attention. QK 1-pass (Q,K hi). PV 2-pass (P split regs, V hi).
// grid (Ntok/128, BHh), 256 threads, warp = 16 q rows.
// ---------------------------------------------------------------------------
#define FA_PITCH  72
#define FA_VPITCH 136
#define FA_QT     (128*FA_PITCH)  // 9216 halves
#define FA_VT     (64*FA_VPITCH)  // 8704 halves
#define FA_KBASE  (FA_QT)
#define FA_VBASE  (3*FA_QT)
#define FA_SMEM_BYTES ((3*FA_QT + 2*FA_VT)*2)   // 90112 B

__global__ void __launch_bounds__(256) flash_attn(
    const half* __restrict__ qh, const half* __restrict__ kh,
    const half* __restrict__ vth, half* __restrict__ atth)
{
    extern __shared__ half sm[];
    uint32_t smBase = smem_u32(sm);
    int tid = threadIdx.x, lane = tid & 31, wid = tid >> 5;

    int bh = blockIdx.y;
    int b = bh >> 4, h = bh & 15;
    int q0 = blockIdx.x * 128;
    int qg0 = b * Ntok + q0;
    int kg0 = b * Ntok;
    int hcol = h * 64;
    size_t vbase = (size_t)bh * 64 * Ntok;

    auto ldQ = [&]() {
        #pragma unroll
        for (int i = 0; i < 4; i++) {
            int seg = tid + (i << 8);           // 0..1023
            int row = seg >> 3;
            int cs = (seg & 7) << 3;
            const half* src = qh + (size_t)(qg0 + row) * Ii + hcol + cs;
            uint32_t dst = smBase + (uint32_t)((row * FA_PITCH + cs) * 2);
            CP_ASYNC16(dst, src);
        }
    };
    auto ldKV = [&](int chunk, int s) {
        int key0 = chunk << 7;
        #pragma unroll
        for (int i = 0; i < 8; i++) {
            int seg = tid + (i << 8);           // 0..2047
            int t = seg >> 10;                  // 0 Kh, 1 Vh
            int w = seg & 1023;
            if (t == 0) {
                int row = w >> 3;
                int cs = (w & 7) << 3;
                const half* src = kh + (size_t)(kg0 + key0 + row) * Ii + hcol + cs;
                uint32_t dst = smBase + (uint32_t)((FA_KBASE + s * FA_QT + row * FA_PITCH + cs) * 2);
                CP_ASYNC16(dst, src);
            } else {
                int row = w >> 4;
                int cs = (w & 15) << 3;
                const half* src = vth + vbase + (size_t)row * Ntok + key0 + cs;
                uint32_t dst = smBase + (uint32_t)((FA_VBASE + s * FA_VT + row * FA_VPITCH + cs) * 2);
                CP_ASYNC16(dst, src);
            }
        }
    };

    int aRow = (lane & 7) + ((lane >> 3) & 1) * 8;
    int aCg  = (lane >> 4) * 8;
    int bRow = (lane & 7) + (lane >> 4) * 8;
    int bCg  = ((lane >> 3) & 1) * 8;

    float O[8][4];
    #pragma unroll
    for (int i = 0; i < 8; i++)
        #pragma unroll
        for (int e = 0; e < 4; e++) O[i][e] = 0.f;
    float M0 = -1e30f, M1 = -1e30f, L0 = 0.f, L1 = 0.f;

    ldQ(); ldKV(0, 0);
    CP_COMMIT();
    ldKV(1, 1);
    CP_COMMIT();

    for (int c = 0; c < 16; c++) {
        if (c < 15) asm volatile("cp.async.wait_group 1;" ::: "memory");
        else        asm volatile("cp.async.wait_group 0;" ::: "memory");
        __syncthreads();

        int s = c & 1;
        // ---- S = Q K^T (pre-scaled), 16x128 per warp, 1-pass ----
        float S[16][4];
        #pragma unroll
        for (int i = 0; i < 16; i++)
            #pragma unroll
            for (int e = 0; e < 4; e++) S[i][e] = 0.f;

        uint32_t kTile = smBase + (uint32_t)((FA_KBASE + s * FA_QT) * 2);
        #pragma unroll
        for (int ks = 0; ks < 4; ks++) {
            uint32_t aH[4];
            uint32_t addrA = smBase + (uint32_t)(((wid * 16 + aRow) * FA_PITCH + ks * 16 + aCg) * 2);
            LDSM4(aH[0], aH[1], aH[2], aH[3], addrA);
            #pragma unroll
            for (int nn = 0; nn < 8; nn++) {
                uint32_t addrB = kTile + (uint32_t)(((nn * 16 + bRow) * FA_PITCH + ks * 16 + bCg) * 2);
                uint32_t bH[4];
                LDSM4(bH[0], bH[1], bH[2], bH[3], addrB);
                MMA16816(S[2 * nn],     aH, bH[0], bH[1]);
                MMA16816(S[2 * nn + 1], aH, bH[2], bH[3]);
            }
        }

        // ---- online softmax ----
        float cm0 = -1e30f, cm1 = -1e30f;
        #pragma unroll
        for (int i = 0; i < 16; i++) {
            cm0 = fmaxf(cm0, fmaxf(S[i][0], S[i][1]));
            cm1 = fmaxf(cm1, fmaxf(S[i][2], S[i][3]));
        }
        #pragma unroll
        for (int o = 1; o <= 2; o <<= 1) {
            cm0 = fmaxf(cm0, __shfl_xor_sync(0xffffffffu, cm0, o));
            cm1 = fmaxf(cm1, __shfl_xor_sync(0xffffffffu, cm1, o));
        }
        float nM0 = fmaxf(M0, cm0), nM1 = fmaxf(M1, cm1);
        float f0 = __expf(M0 - nM0), f1 = __expf(M1 - nM1);
        M0 = nM0; M1 = nM1;
        #pragma unroll
        for (int i = 0; i < 8; i++) {
            O[i][0] *= f0; O[i][1] *= f0; O[i][2] *= f1; O[i][3] *= f1;
        }
        float l0 = 0.f, l1 = 0.f;
        #pragma unroll
        for (int i = 0; i < 16; i++) {
            S[i][0] = __expf(S[i][0] - nM0);
            S[i][1] = __expf(S[i][1] - nM0);
            S[i][2] = __expf(S[i][2] - nM1);
            S[i][3] = __expf(S[i][3] - nM1);
            l0 += S[i][0] + S[i][1];
            l1 += S[i][2] + S[i][3];
        }
        #pragma unroll
        for (int o = 1; o <= 2; o <<= 1) {
            l0 += __shfl_xor_sync(0xffffffffu, l0, o);
            l1 += __shfl_xor_sync(0xffffffffu, l1, o);
        }
        L0 = L0 * f0 + l0;
        L1 = L1 * f1 + l1;

        // ---- O += P @ V (P split in registers, V hi-only) ----
        uint32_t vTile = smBase + (uint32_t)((FA_VBASE + s * FA_VT) * 2);
        #pragma unroll
        for (int kk = 0; kk < 8; kk++) {
            uint32_t PhF[4], PlF[4];
            #pragma unroll
            for (int u = 0; u < 2; u++) {
                int t = 2 * kk + u;
                half2 h01 = __floats2half2_rn(S[t][0], S[t][1]);
                half2 h23 = __floats2half2_rn(S[t][2], S[t][3]);
                float r0a = S[t][0] - __low2float(h01);
                float r0b = S[t][1] - __high2float(h01);
                float r1a = S[t][2] - __low2float(h23);
                float r1b = S[t][3] - __high2float(h23);
                half2 lo01 = __floats2half2_rn(r0a, r0b);
                half2 lo23 = __floats2half2_rn(r1a, r1b);
                PhF[2 * u]     = *reinterpret_cast<uint32_t*>(&h01);
                PhF[2 * u + 1] = *reinterpret_cast<uint32_t*>(&h23);
                PlF[2 * u]     = *reinterpret_cast<uint32_t*>(&lo01);
                PlF[2 * u + 1] = *reinterpret_cast<uint32_t*>(&lo23);
            }
            #pragma unroll
            for (int nn = 0; nn < 4; nn++) {
                uint32_t addrV = vTile + (uint32_t)(((nn * 16 + bRow) * FA_VPITCH + kk * 16 + bCg) * 2);
                uint32_t vH[4];
                LDSM4(vH[0], vH[1], vH[2], vH[3], addrV);
                MMA16816(O[2 * nn],     PhF, vH[0], vH[1]);
                MMA16816(O[2 * nn + 1], PhF, vH[2], vH[3]);
                MMA16816(O[2 * nn],     PlF, vH[0], vH[1]);
                MMA16816(O[2 * nn + 1], PlF, vH[2], vH[3]);
            }
        }

        __syncthreads();
        if (c + 2 < 16) { ldKV(c + 2, s); CP_COMMIT(); }
    }

    // ---- finalize ----
    float inv0 = 1.f / L0, inv1 = 1.f / L1;
    int r0 = qg0 + wid * 16 + (lane >> 2);
    int r1 = r0 + 8;
    #pragma unroll
    for (int nf = 0; nf < 8; nf++) {
        int d0 = nf * 8 + (lane & 3) * 2;
        *reinterpret_cast<half2*>(atth + (size_t)r0 * Ii + hcol + d0) =
            __floats2half2_rn(O[nf][0] * inv0, O[nf][1] * inv0);
        *reinterpret_cast<half2*>(atth + (size_t)r1 * Ii + hcol + d0) =
            __floats2half2_rn(O[nf][2] * inv1, O[nf][3] * inv1);
    }
}

// ---------------------------------------------------------------------------
// LayerNorm -> fp16 (hi only)
// ---------------------------------------------------------------------------
__global__ __launch_bounds__(256) void ln_kernel(
    const float* __restrict__ x, const float* __restrict__ g, const float* __restrict__ b,
    half* __restrict__ oh)
{
    size_t row = blockIdx.x;
    const float* xr = x + row * Dm;
    __shared__ float red[256];
    int t = threadIdx.x;
    float v[4];
    float s = 0.f;
    #pragma unroll
    for (int j = 0; j < 4; j++) { v[j] = xr[t + j * 256]; s += v[j]; }
    red[t] = s; __syncthreads();
    for (int o = 128; o > 0; o >>= 1) { if (t < o) red[t] += red[t + o]; __syncthreads(); }
    float mean = red[0] * (1.f / Dm);
    __syncthreads();
    float s2 = 0.f;
    #pragma unroll
    for (int j = 0; j < 4; j++) { float d = v[j] - mean; s2 += d * d; }
    red[t] = s2; __syncthreads();
    for (int o = 128; o > 0; o >>= 1) { if (t < o) red[t] += red[t + o]; __syncthreads(); }
    float inv = rsqrtf(red[0] * (1.f / Dm) + 1e-5f);
    #pragma unroll
    for (int j = 0; j < 4; j++) {
        int i = t + j * 256;
        oh[row * Dm + i] = __float2half_rn((v[j] - mean) * inv * g[i] + b[i]);
    }
}

// ---------------------------------------------------------------------------
// Softmax -> split fp16 (cross-attn)
// ---------------------------------------------------------------------------
__global__ __launch_bounds__(256) void softmax_split_kernel(
    const float* __restrict__ s, half* __restrict__ ph, half* __restrict__ pl,
    int cols, int ldin, int ldout)
{
    size_t row = blockIdx.x;
    const float* r = s + row * (size_t)ldin;
    __shared__ float red[256];
    int t = threadIdx.x;
    float v = (t < cols) ? r[t] : -INFINITY;
    red[t] = v; __syncthreads();
    for (int o = 128; o > 0; o >>= 1) { if (t < o) red[t] = fmaxf(red[t], red[t + o]); __syncthreads(); }
    float m = red[0]; __syncthreads();
    float e = (t < cols) ? __expf(v - m) : 0.f;
    red[t] = e; __syncthreads();
    for (int o = 128; o > 0; o >>= 1) { if (t < o) red[t] += red[t + o]; __syncthreads(); }
    float inv = 1.f / red[0];
    if (t < ldout) {
        half h, l; split2(e * inv, h, l);
        ph[row * (size_t)ldout + t] = h;
        pl[row * (size_t)ldout + t] = l;
    }
}

// ---------------------------------------------------------------------------
// GEGLU -> fp16
// ---------------------------------------------------------------------------
__global__ __launch_bounds__(256) void geglu_kernel(
    const float* __restrict__ hg, half* __restrict__ oh)
{
    size_t idx = (size_t)blockIdx.x * 256 + threadIdx.x;
    if (idx >= (size_t)BN * FFd) return;
    size_t r = idx / FFd; int c = (int)(idx % FFd);
    float h = hg[r * (2 * FFd) + c];
    float g = hg[r * (2 * FFd) + FFd + c];
    float gl = 0.5f * g * (1.f + erff(g * 0.70710678118654752440f));
    oh[idx] = __float2half_rn(h * gl);
}

// ---------------------------------------------------------------------------
// Plain fp32 -> fp16
// ---------------------------------------------------------------------------
__global__ __launch_bounds__(256) void tohalf_kernel(
    const float* __restrict__ src, half* __restrict__ dh, long long n)
{
    long long i = (long long)blockIdx.x * 256 + threadIdx.x;
    if (i >= n) return;
    dh[i] = __float2half_rn(src[i]);
}

// ---------------------------------------------------------------------------
// Transpose: src [R x C] fp32 -> dst [C x R] fp16
// ---------------------------------------------------------------------------
__global__ __launch_bounds__(1024) void thalf_kernel(
    const float* __restrict__ src, half* __restrict__ dh, int R, int C)
{
    __shared__ float tile[32][33];
    int c0 = blockIdx.x * 32, r0 = blockIdx.y * 32;
    int tx = threadIdx.x, ty = threadIdx.y;
    int r = r0 + ty, c = c0 + tx;
    tile[ty][tx] = (r < R && c < C) ? src[(size_t)r * C + c] : 0.f;
    __syncthreads();
    int rr = r0 + tx, cc = c0 + ty;
    if (rr < R && cc < C)
        dh[(size_t)cc * R + rr] = __float2half_rn(tile[tx][ty]);
}

// ---------------------------------------------------------------------------
// Per-head transpose of V (hi only)
// ---------------------------------------------------------------------------
__global__ __launch_bounds__(1024) void head_t_kernel(
    const float* __restrict__ src, half* __restrict__ dh,
    int T, int Tpad)
{
    __shared__ float tile[32][33];
    int zh = blockIdx.z;
    int b = zh >> 4, h = zh & 15;
    int tx = threadIdx.x, ty = threadIdx.y;
    int t0 = blockIdx.x * 32, d0 = blockIdx.y * 32;
    int t = t0 + ty, d = d0 + tx;
    tile[ty][tx] = (t < T) ? src[((size_t)b * T + t) * 1024 + h * 64 + d] : 0.f;
    __syncthreads();
    int dd = d0 + ty, tt = t0 + tx;
    if (tt < Tpad) {
        size_t base = (size_t)zh * 64 * Tpad + (size_t)dd * Tpad + tt;
        dh[base] = __float2half_rn(tile[tx][ty]);
    }
}

// ---------------------------------------------------------------------------
// Orchestration
// ---------------------------------------------------------------------------
static inline dim3 ggrid(int M, int N, int z) { return dim3((N + 127) / 128, (M + 127) / 128, z); }

#define SYM(p, s) cudaGetSymbolAddress((void**)&p, s)

extern "C" void kernel_launch(void* const* d_in, const int* in_sizes, int n_in,
                              void* d_out, int out_size)
{
    const float* x     = (const float*)d_in[0];
    const float* ctx   = (const float*)d_in[1];
    const float* ln1_g = (const float*)d_in[2];
    const float* ln1_b = (const float*)d_in[3];
    const float* ln2_g = (const float*)d_in[4];
    const float* ln2_b = (const float*)d_in[5];
    const float* ln3_g = (const float*)d_in[6];
    const float* ln3_b = (const float*)d_in[7];
    const float* Wq1   = (const float*)d_in[8];
    const float* Wk1   = (const float*)d_in[9];
    const float* Wv1   = (const float*)d_in[10];
    const float* Wo1   = (const float*)d_in[11];
    const float* bo1   = (const float*)d_in[12];
    const float* Wq2   = (const float*)d_in[13];
    const float* Wk2   = (const float*)d_in[14];
    const float* Wv2   = (const float*)d_in[15];
    const float* Wo2   = (const float*)d_in[16];
    const float* bo2   = (const float*)d_in[17];
    const float* Wff1  = (const float*)d_in[18];
    const float* bff1  = (const float*)d_in[19];
    const float* Wff2  = (const float*)d_in[20];
    const float* bff2  = (const float*)d_in[21];
    float* out = (float*)d_out;

    half *lnh,*qh,*kh,*vth,*Ph,*Pl,*atth,*ctxh,*ffh;
    half *wq1h,*wk1h,*wv1h,*wo1h,*wq2h,*wk2h,*wv2h,*wo2h,*wf1h,*wf2h;
    float *v,*sim,*x1,*x2,*hg;
    SYM(lnh,g_lnh); SYM(qh,g_qh); SYM(kh,g_kh);
    SYM(v,g_v); SYM(vth,g_vth); SYM(sim,g_sim); SYM(Ph,g_Ph); SYM(Pl,g_Pl);
    SYM(atth,g_atth); SYM(x1,g_x1); SYM(x2,g_x2);
    SYM(ctxh,g_ctxh); SYM(hg,g_hg); SYM(ffh,g_ffh);
    SYM(wq1h,g_wq1h); SYM(wk1h,g_wk1h); SYM(wv1h,g_wv1h); SYM(wo1h,g_wo1h);
    SYM(wq2h,g_wq2h); SYM(wk2h,g_wk2h); SYM(wv2h,g_wv2h); SYM(wo2h,g_wo2h);
    SYM(wf1h,g_wf1h); SYM(wf2h,g_wf2h);

    cudaFuncSetAttribute(mma_gemm<0>, cudaFuncAttributeMaxDynamicSharedMemorySize, SMEM_G1);
    cudaFuncSetAttribute(mma_gemm<1>, cudaFuncAttributeMaxDynamicSharedMemorySize, SMEM_G2);
    cudaFuncSetAttribute(flash_attn, cudaFuncAttributeMaxDynamicSharedMemorySize, FA_SMEM_BYTES);

    dim3 tb(32, 32);
    // ---- weight transposes (hi only) ----
    thalf_kernel<<<dim3(Ii/32, Dm/32), tb>>>(Wq1, wq1h, Dm, Ii);
    thalf_kernel<<<dim3(Ii/32, Dm/32), tb>>>(Wk1, wk1h, Dm, Ii);
    thalf_kernel<<<dim3(Ii/32, Dm/32), tb>>>(Wv1, wv1h, Dm, Ii);
    thalf_kernel<<<dim3(Dm/32, Ii/32), tb>>>(Wo1, wo1h, Ii, Dm);
    thalf_kernel<<<dim3(Ii/32, Dm/32), tb>>>(Wq2, wq2h, Dm, Ii);
    thalf_kernel<<<dim3(Ii/32, DCc/32), tb>>>(Wk2, wk2h, DCc, Ii);
    thalf_kernel<<<dim3(Ii/32, DCc/32), tb>>>(Wv2, wv2h, DCc, Ii);
    thalf_kernel<<<dim3(Dm/32, Ii/32), tb>>>(Wo2, wo2h, Ii, Dm);
    thalf_kernel<<<dim3((2*FFd)/32, Dm/32), tb>>>(Wff1, wf1h, Dm, 2*FFd);
    thalf_kernel<<<dim3(Dm/32, FFd/32), tb>>>(Wff2, wf2h, FFd, Dm);
    tohalf_kernel<<<(BM2*DCc + 255)/256, 256>>>(ctx, ctxh, (long long)BM2*DCc);

    // ================= block 1: self-attention =================
    ln_kernel<<<BN, 256>>>(x, ln1_g, ln1_b, lnh);

    mma_gemm<0><<<ggrid(BN, Ii, 1), 256, SMEM_G1>>>(lnh, nullptr, wq1h, nullptr, nullptr,
        nullptr, qh, BN, Ii, Dm, Dm, Dm, Ii, 0,0,0,0,0,0, 1, SCALE);
    mma_gemm<0><<<ggrid(BN, Ii, 1), 256, SMEM_G1>>>(lnh, nullptr, wk1h, nullptr, nullptr,
        nullptr, kh, BN, Ii, Dm, Dm, Dm, Ii, 0,0,0,0,0,0, 1, 1.f);
    mma_gemm<0><<<ggrid(BN, Ii, 1), 256, SMEM_G1>>>(lnh, nullptr, wv1h, nullptr, nullptr,
        v, nullptr, BN, Ii, Dm, Dm, Dm, Ii, 0,0,0,0,0,0, 1, 1.f);

    head_t_kernel<<<dim3(Ntok/32, 2, BHh), tb>>>(v, vth, Ntok, Ntok);

    flash_attn<<<dim3(Ntok/128, BHh), 256, FA_SMEM_BYTES>>>(qh, kh, vth, atth);

    // x1 = att @ Wo1 + bo1 + x
    mma_gemm<0><<<ggrid(BN, Dm, 1), 256, SMEM_G1>>>(atth, nullptr, wo1h, bo1, x,
        x1, nullptr, BN, Dm, Ii, Ii, Ii, Dm, 0,0,0,0,0,0, 1, 1.f);

    // ================= block 2: cross-attention =================
    ln_kernel<<<BN, 256>>>(x1, ln2_g, ln2_b, lnh);

    mma_gemm<0><<<ggrid(BN, Ii, 1), 256, SMEM_G1>>>(lnh, nullptr, wq2h, nullptr, nullptr,
        nullptr, qh, BN, Ii, Dm, Dm, Dm, Ii, 0,0,0,0,0,0, 1, SCALE);
    mma_gemm<0><<<ggrid(BM2, Ii, 1), 256, SMEM_G1>>>(ctxh, nullptr, wk2h, nullptr, nullptr,
        nullptr, kh, BM2, Ii, DCc, DCc, DCc, Ii, 0,0,0,0,0,0, 1, 1.f);
    mma_gemm<0><<<ggrid(BM2, Ii, 1), 256, SMEM_G1>>>(ctxh, nullptr, wv2h, nullptr, nullptr,
        v, nullptr, BM2, Ii, DCc, DCc, DCc, Ii, 0,0,0,0,0,0, 1, 1.f);

    head_t_kernel<<<dim3((MctxP+31)/32, 2, BHh), tb>>>(v, vth, Mctx, MctxP);

    // sim2 = Q2 K2^T (q pre-scaled)
    mma_gemm<0><<<ggrid(Ntok, Mctx, BHh), 256, SMEM_G1>>>(qh, nullptr, kh, nullptr, nullptr,
        sim, nullptr, Ntok, Mctx, DHd, Ii, Ii, MctxP,
        (long long)Ntok*Ii, 64, (long long)Mctx*Ii, 64,
        (long long)Hh*Ntok*MctxP, (long long)Ntok*MctxP, Hh, 1.f);

    softmax_split_kernel<<<BHh*Ntok, 256>>>(sim, Ph, Pl, Mctx, MctxP, MctxP);

    // att = P2 @ V2 (P split, 2-pass)
    mma_gemm<1><<<ggrid(Ntok, DHd, BHh), 256, SMEM_G2>>>(Ph, Pl, vth, nullptr, nullptr,
        nullptr, atth, Ntok, DHd, MctxP, MctxP, MctxP, Ii,
        (long long)Hh*Ntok*MctxP, (long long)Ntok*MctxP,
        (long long)Hh*DHd*MctxP, (long long)DHd*MctxP,
        (long long)Ntok*Ii, 64, Hh, 1.f);

    // x2 = att @ Wo2 + bo2 + x1
    mma_gemm<0><<<ggrid(BN, Dm, 1), 256, SMEM_G1>>>(atth, nullptr, wo2h, bo2, x1,
        x2, nullptr, BN, Dm, Ii, Ii, Ii, Dm, 0,0,0,0,0,0, 1, 1.f);

    // ================= block 3: GEGLU FF =================
    ln_kernel<<<BN, 256>>>(x2, ln3_g, ln3_b, lnh);

    mma_gemm<0><<<ggrid(BN, 2*FFd, 1), 256, SMEM_G1>>>(lnh, nullptr, wf1h, bff1, nullptr,
        hg, nullptr, BN, 2*FFd, Dm, Dm, Dm, 2*FFd, 0,0,0,0,0,0, 1, 1.f);

    geglu_kernel<<<(int)(((long long)BN*FFd + 255)/256), 256>>>(hg, ffh);

    mma_gemm<0><<<ggrid(BN, Dm, 1), 256, SMEM_G1>>>(ffh, nullptr, wf2h, bff2, x2,
        out, nullptr, BN, Dm, FFd, FFd, FFd, Dm, 0,0,0,0,0,0, 1, 1.f);
}

// round 7
// speedup vs baseline: 7.9233x; 1.1111x over previous
#include <cuda_runtime.h>
#include <cuda_fp16.h>
#include <math.h>
#include <stdint.h>

// ---------------------------------------------------------------------------
// Problem constants
// ---------------------------------------------------------------------------
#define Bsz   2
#define Ntok  2048
#define Dm    1024
#define Hh    16
#define DHd   64
#define Ii    1024
#define DCc   768
#define Mctx  77
#define MctxP 80
#define FFd   4096
#define BN    (Bsz*Ntok)
#define BM2   (Bsz*Mctx)
#define BHh   (Bsz*Hh)
#define SCALE 0.125f

// ---------------------------------------------------------------------------
// Device scratch
// ---------------------------------------------------------------------------
#define DEVARR(name, type, count) __device__ __align__(16) type name[(size_t)(count)]

DEVARR(g_lnh,  half, BN*Dm);
DEVARR(g_qh,   half, BN*Ii);
DEVARR(g_kh,   half, BN*Ii);
DEVARR(g_v,    float, BN*Ii);
DEVARR(g_vth,  half, BHh*DHd*Ntok);
DEVARR(g_sim,  float, (size_t)BHh*Ntok*MctxP);
DEVARR(g_Ph,   half, (size_t)BHh*Ntok*MctxP); DEVARR(g_Pl, half, (size_t)BHh*Ntok*MctxP);
DEVARR(g_atth, half, BN*Ii);
DEVARR(g_x1,   float, BN*Dm);  DEVARR(g_x2,   float, BN*Dm);
DEVARR(g_ctxh, half, BM2*DCc);
DEVARR(g_ffh,  half, (size_t)BN*FFd);
// transposed weights [N x K], hi only
DEVARR(g_wq1h, half, Dm*Ii);
DEVARR(g_wk1h, half, Dm*Ii);
DEVARR(g_wv1h, half, Dm*Ii);
DEVARR(g_wo1h, half, Dm*Ii);
DEVARR(g_wq2h, half, Dm*Ii);
DEVARR(g_wk2h, half, DCc*Ii);
DEVARR(g_wv2h, half, DCc*Ii);
DEVARR(g_wo2h, half, Dm*Ii);
DEVARR(g_wf1h, half, (size_t)Dm*2*FFd);   // interleaved: row 2j=h, 2j+1=gate
DEVARR(g_wf2h, half, (size_t)FFd*Dm);

// ---------------------------------------------------------------------------
// Helpers
// ---------------------------------------------------------------------------
__device__ __forceinline__ uint32_t smem_u32(const void* p) {
    uint32_t a;
    asm("{ .reg .u64 t; cvta.to.shared.u64 t, %1; cvt.u32.u64 %0, t; }" : "=r"(a) : "l"(p));
    return a;
}
__device__ __forceinline__ void split2(float x, half& h, half& l) {
    h = __float2half_rn(x);
    l = __float2half_rn(x - __half2float(h));
}
__device__ __forceinline__ float gelu_exact(float g) {
    return 0.5f * g * (1.f + erff(g * 0.70710678118654752440f));
}

#define LDSM4(r0, r1, r2, r3, addr) \
    asm volatile("ldmatrix.sync.aligned.m8n8.x4.shared.b16 {%0,%1,%2,%3}, [%4];" \
        : "=r"(r0), "=r"(r1), "=r"(r2), "=r"(r3) : "r"(addr))

#define MMA16816(c, a, b0, b1) \
    asm volatile("mma.sync.aligned.m16n8k16.row.col.f32.f16.f16.f32 " \
        "{%0,%1,%2,%3}, {%4,%5,%6,%7}, {%8,%9}, {%0,%1,%2,%3};" \
        : "+f"((c)[0]), "+f"((c)[1]), "+f"((c)[2]), "+f"((c)[3]) \
        : "r"((a)[0]), "r"((a)[1]), "r"((a)[2]), "r"((a)[3]), "r"(b0), "r"(b1))

#define CP_ASYNC16(dst, src) \
    asm volatile("cp.async.cg.shared.global [%0], [%1], 16;" :: "r"(dst), "l"(src) : "memory")
#define CP_COMMIT() asm volatile("cp.async.commit_group;" ::: "memory")

// ---------------------------------------------------------------------------
// mma.sync GEMM: C = alpha * A @ Bh^T (+bias)(+resid)
// SPLIT_A: A = Ah+Al (2-pass) vs Ah (1-pass).
// GEGLU: epilogue pairs adjacent cols (h, gate) -> Ch[rr*ldc + gc/2] = h*gelu(g).
//        bias is the raw bff1 (h part at [j], gate part at [FFd+j]).
// ---------------------------------------------------------------------------
#define PITCH   40
#define TILE_H  (128*PITCH)          // 5120 halves

template<int SPLIT_A, int GEGLU>
__global__ void __launch_bounds__(256) mma_gemm(
    const half* __restrict__ Ah_, const half* __restrict__ Al_,
    const half* __restrict__ Bh_,
    const float* __restrict__ bias, const float* __restrict__ resid,
    float* __restrict__ C, half* __restrict__ Ch,
    int M, int N, int K, int lda, int ldb, int ldc,
    long long aO, long long aI, long long bO, long long bI,
    long long cO, long long cI, int nInner, float alpha)
{
    constexpr int NT = 2 + SPLIT_A;           // tiles per stage
    extern __shared__ half sm[];
    uint32_t smBase = smem_u32(sm);
    int tid = threadIdx.x, lane = tid & 31, wid = tid >> 5;
    int warpM = wid >> 1, warpN = wid & 1;

    int z = blockIdx.z, zo = z / nInner, zi = z % nInner;
    const half* Ahp = Ah_ + (long long)zo * aO + (long long)zi * aI;
    const half* Alp = SPLIT_A ? (Al_ + (long long)zo * aO + (long long)zi * aI) : nullptr;
    const half* Bhp = Bh_ + (long long)zo * bO + (long long)zi * bI;
    long long offC = (long long)zo * cO + (long long)zi * cI;

    int rowBase = blockIdx.y * 128, colBase = blockIdx.x * 128;

    float acc[2][8][4];
    #pragma unroll
    for (int i = 0; i < 2; i++)
        #pragma unroll
        for (int j = 0; j < 8; j++)
            #pragma unroll
            for (int e = 0; e < 4; e++) acc[i][j][e] = 0.f;

    int nc = (K + 31) >> 5;

    auto load_stage = [&](int c, int s) {
        int k0 = c << 5;
        #pragma unroll
        for (int i = 0; i < 2 * NT; i++) {
            int seg  = tid + (i << 8);
            int tile = seg >> 9;
            int w    = seg & 511;
            int row  = w >> 2;
            int cs   = (w & 3) << 3;
            bool isA = tile < (NT - 1);
            const half* base = (tile == 0) ? Ahp : (SPLIT_A && tile == 1) ? Alp : Bhp;
            int ld  = isA ? lda : ldb;
            int gr  = (isA ? rowBase : colBase) + row;
            int gk  = k0 + cs;
            bool ok = (gr < (isA ? M : N)) && (gk + 8 <= K);
            const half* src = ok ? (base + (size_t)gr * ld + gk) : base;
            uint32_t dst = smBase + (uint32_t)(((s * NT + tile) * TILE_H + row * PITCH + cs) * 2);
            uint32_t sz = ok ? 16u : 0u;
            asm volatile("cp.async.cg.shared.global [%0], [%1], 16, %2;"
                         :: "r"(dst), "l"(src), "r"(sz) : "memory");
        }
    };

    int aRow = (lane & 7) + ((lane >> 3) & 1) * 8;
    int aCg  = (lane >> 4) * 8;
    int bRow = (lane & 7) + (lane >> 4) * 8;
    int bCg  = ((lane >> 3) & 1) * 8;

    auto compute_stage = [&](int s) {
        uint32_t sBase = smBase + (uint32_t)(s * NT * TILE_H * 2);
        #pragma unroll
        for (int ks = 0; ks < 2; ks++) {
            uint32_t ah[2][4], al[2][4];
            #pragma unroll
            for (int mm = 0; mm < 2; mm++) {
                uint32_t addr = sBase + (uint32_t)(((warpM * 32 + mm * 16 + aRow) * PITCH + ks * 16 + aCg) * 2);
                LDSM4(ah[mm][0], ah[mm][1], ah[mm][2], ah[mm][3], addr);
                if (SPLIT_A) LDSM4(al[mm][0], al[mm][1], al[mm][2], al[mm][3], addr + TILE_H * 2);
            }
            #pragma unroll
            for (int nn = 0; nn < 4; nn++) {
                uint32_t baddr = sBase + (uint32_t)(((NT - 1) * TILE_H + (warpN * 64 + nn * 16 + bRow) * PITCH + ks * 16 + bCg) * 2);
                uint32_t bh[4];
                LDSM4(bh[0], bh[1], bh[2], bh[3], baddr);
                #pragma unroll
                for (int mm = 0; mm < 2; mm++) {
                    MMA16816(acc[mm][2 * nn],     ah[mm], bh[0], bh[1]);
                    MMA16816(acc[mm][2 * nn + 1], ah[mm], bh[2], bh[3]);
                    if (SPLIT_A) {
                        MMA16816(acc[mm][2 * nn],     al[mm], bh[0], bh[1]);
                        MMA16816(acc[mm][2 * nn + 1], al[mm], bh[2], bh[3]);
                    }
                }
            }
        }
    };

    load_stage(0, 0);
    CP_COMMIT();
    for (int c = 0; c < nc; c++) {
        if (c + 1 < nc) load_stage(c + 1, (c + 1) & 1);
        CP_COMMIT();
        asm volatile("cp.async.wait_group 1;" ::: "memory");
        __syncthreads();
        compute_stage(c & 1);
        __syncthreads();
    }

    if (GEGLU) {
        // cols come in (h, gate) pairs; output col j = gc/2, width ldc (=FFd)
        #pragma unroll
        for (int mm = 0; mm < 2; mm++) {
            #pragma unroll
            for (int nf = 0; nf < 8; nf++) {
                int rr = rowBase + warpM * 32 + mm * 16 + (lane >> 2);
                int gc = colBase + warpN * 64 + nf * 8 + (lane & 3) * 2;
                int j  = gc >> 1;
                float bh_ = bias[j], bg_ = bias[FFd + j];
                float h0 = acc[mm][nf][0] + bh_;
                float g0 = acc[mm][nf][1] + bg_;
                Ch[(size_t)rr * ldc + j] = __float2half_rn(h0 * gelu_exact(g0));
                float h1 = acc[mm][nf][2] + bh_;
                float g1 = acc[mm][nf][3] + bg_;
                Ch[(size_t)(rr + 8) * ldc + j] = __float2half_rn(h1 * gelu_exact(g1));
            }
        }
    } else {
        #pragma unroll
        for (int mm = 0; mm < 2; mm++) {
            #pragma unroll
            for (int nf = 0; nf < 8; nf++) {
                int r  = rowBase + warpM * 32 + mm * 16 + (lane >> 2);
                int cc = colBase + warpN * 64 + nf * 8 + (lane & 3) * 2;
                #pragma unroll
                for (int e = 0; e < 4; e++) {
                    int rr = r + (e >> 1) * 8;
                    int gc = cc + (e & 1);
                    if (rr < M && gc < N) {
                        float v = acc[mm][nf][e] * alpha;
                        if (bias) v += bias[gc];
                        size_t idx = (size_t)offC + (size_t)rr * ldc + gc;
                        if (resid) v += resid[idx];
                        if (C) C[idx] = v;
                        if (Ch) Ch[idx] = __float2half_rn(v);
                    }
                }
            }
        }
    }
}

#define SMEM_G1 (2*2*TILE_H*2)   // 40960 B
#define SMEM_G2 (2*3*TILE_H*2)   // 61440 B

// ---------------------------------------------------------------------------
// Fused flash self-attention. QK 1-pass, PV 1-pass (P hi-only).
// ---------------------------------------------------------------------------
#define FA_PITCH  72
#define FA_VPITCH 136
#define FA_QT     (128*FA_PITCH)
#define FA_VT     (64*FA_VPITCH)
#define FA_KBASE  (FA_QT)
#define FA_VBASE  (3*FA_QT)
#define FA_SMEM_BYTES ((3*FA_QT + 2*FA_VT)*2)   // 90112 B

__global__ void __launch_bounds__(256) flash_attn(
    const half* __restrict__ qh, const half* __restrict__ kh,
    const half* __restrict__ vth, half* __restrict__ atth)
{
    extern __shared__ half sm[];
    uint32_t smBase = smem_u32(sm);
    int tid = threadIdx.x, lane = tid & 31, wid = tid >> 5;

    int bh = blockIdx.y;
    int b = bh >> 4, h = bh & 15;
    int q0 = blockIdx.x * 128;
    int qg0 = b * Ntok + q0;
    int kg0 = b * Ntok;
    int hcol = h * 64;
    size_t vbase = (size_t)bh * 64 * Ntok;

    auto ldQ = [&]() {
        #pragma unroll
        for (int i = 0; i < 4; i++) {
            int seg = tid + (i << 8);
            int row = seg >> 3;
            int cs = (seg & 7) << 3;
            const half* src = qh + (size_t)(qg0 + row) * Ii + hcol + cs;
            uint32_t dst = smBase + (uint32_t)((row * FA_PITCH + cs) * 2);
            CP_ASYNC16(dst, src);
        }
    };
    auto ldKV = [&](int chunk, int s) {
        int key0 = chunk << 7;
        #pragma unroll
        for (int i = 0; i < 8; i++) {
            int seg = tid + (i << 8);
            int t = seg >> 10;                  // 0 Kh, 1 Vh
            int w = seg & 1023;
            if (t == 0) {
                int row = w >> 3;
                int cs = (w & 7) << 3;
                const half* src = kh + (size_t)(kg0 + key0 + row) * Ii + hcol + cs;
                uint32_t dst = smBase + (uint32_t)((FA_KBASE + s * FA_QT + row * FA_PITCH + cs) * 2);
                CP_ASYNC16(dst, src);
            } else {
                int row = w >> 4;
                int cs = (w & 15) << 3;
                const half* src = vth + vbase + (size_t)row * Ntok + key0 + cs;
                uint32_t dst = smBase + (uint32_t)((FA_VBASE + s * FA_VT + row * FA_VPITCH + cs) * 2);
                CP_ASYNC16(dst, src);
            }
        }
    };

    int aRow = (lane & 7) + ((lane >> 3) & 1) * 8;
    int aCg  = (lane >> 4) * 8;
    int bRow = (lane & 7) + (lane >> 4) * 8;
    int bCg  = ((lane >> 3) & 1) * 8;

    float O[8][4];
    #pragma unroll
    for (int i = 0; i < 8; i++)
        #pragma unroll
        for (int e = 0; e < 4; e++) O[i][e] = 0.f;
    float M0 = -1e30f, M1 = -1e30f, L0 = 0.f, L1 = 0.f;

    ldQ(); ldKV(0, 0);
    CP_COMMIT();
    ldKV(1, 1);
    CP_COMMIT();

    for (int c = 0; c < 16; c++) {
        if (c < 15) asm volatile("cp.async.wait_group 1;" ::: "memory");
        else        asm volatile("cp.async.wait_group 0;" ::: "memory");
        __syncthreads();

        int s = c & 1;
        float S[16][4];
        #pragma unroll
        for (int i = 0; i < 16; i++)
            #pragma unroll
            for (int e = 0; e < 4; e++) S[i][e] = 0.f;

        uint32_t kTile = smBase + (uint32_t)((FA_KBASE + s * FA_QT) * 2);
        #pragma unroll
        for (int ks = 0; ks < 4; ks++) {
            uint32_t aH[4];
            uint32_t addrA = smBase + (uint32_t)(((wid * 16 + aRow) * FA_PITCH + ks * 16 + aCg) * 2);
            LDSM4(aH[0], aH[1], aH[2], aH[3], addrA);
            #pragma unroll
            for (int nn = 0; nn < 8; nn++) {
                uint32_t addrB = kTile + (uint32_t)(((nn * 16 + bRow) * FA_PITCH + ks * 16 + bCg) * 2);
                uint32_t bH[4];
                LDSM4(bH[0], bH[1], bH[2], bH[3], addrB);
                MMA16816(S[2 * nn],     aH, bH[0], bH[1]);
                MMA16816(S[2 * nn + 1], aH, bH[2], bH[3]);
            }
        }

        // ---- online softmax ----
        float cm0 = -1e30f, cm1 = -1e30f;
        #pragma unroll
        for (int i = 0; i < 16; i++) {
            cm0 = fmaxf(cm0, fmaxf(S[i][0], S[i][1]));
            cm1 = fmaxf(cm1, fmaxf(S[i][2], S[i][3]));
        }
        #pragma unroll
        for (int o = 1; o <= 2; o <<= 1) {
            cm0 = fmaxf(cm0, __shfl_xor_sync(0xffffffffu, cm0, o));
            cm1 = fmaxf(cm1, __shfl_xor_sync(0xffffffffu, cm1, o));
        }
        float nM0 = fmaxf(M0, cm0), nM1 = fmaxf(M1, cm1);
        float f0 = __expf(M0 - nM0), f1 = __expf(M1 - nM1);
        M0 = nM0; M1 = nM1;
        #pragma unroll
        for (int i = 0; i < 8; i++) {
            O[i][0] *= f0; O[i][1] *= f0; O[i][2] *= f1; O[i][3] *= f1;
        }
        float l0 = 0.f, l1 = 0.f;
        #pragma unroll
        for (int i = 0; i < 16; i++) {
            S[i][0] = __expf(S[i][0] - nM0);
            S[i][1] = __expf(S[i][1] - nM0);
            S[i][2] = __expf(S[i][2] - nM1);
            S[i][3] = __expf(S[i][3] - nM1);
            l0 += S[i][0] + S[i][1];
            l1 += S[i][2] + S[i][3];
        }
        #pragma unroll
        for (int o = 1; o <= 2; o <<= 1) {
            l0 += __shfl_xor_sync(0xffffffffu, l0, o);
            l1 += __shfl_xor_sync(0xffffffffu, l1, o);
        }
        L0 = L0 * f0 + l0;
        L1 = L1 * f1 + l1;

        // ---- O += P @ V (P hi-only, 1-pass) ----
        uint32_t vTile = smBase + (uint32_t)((FA_VBASE + s * FA_VT) * 2);
        #pragma unroll
        for (int kk = 0; kk < 8; kk++) {
            uint32_t PhF[4];
            #pragma unroll
            for (int u = 0; u < 2; u++) {
                int t = 2 * kk + u;
                half2 h01 = __floats2half2_rn(S[t][0], S[t][1]);
                half2 h23 = __floats2half2_rn(S[t][2], S[t][3]);
                PhF[2 * u]     = *reinterpret_cast<uint32_t*>(&h01);
                PhF[2 * u + 1] = *reinterpret_cast<uint32_t*>(&h23);
            }
            #pragma unroll
            for (int nn = 0; nn < 4; nn++) {
                uint32_t addrV = vTile + (uint32_t)(((nn * 16 + bRow) * FA_VPITCH + kk * 16 + bCg) * 2);
                uint32_t vH[4];
                LDSM4(vH[0], vH[1], vH[2], vH[3], addrV);
                MMA16816(O[2 * nn],     PhF, vH[0], vH[1]);
                MMA16816(O[2 * nn + 1], PhF, vH[2], vH[3]);
            }
        }

        __syncthreads();
        if (c + 2 < 16) { ldKV(c + 2, s); CP_COMMIT(); }
    }

    float inv0 = 1.f / L0, inv1 = 1.f / L1;
    int r0 = qg0 + wid * 16 + (lane >> 2);
    int r1 = r0 + 8;
    #pragma unroll
    for (int nf = 0; nf < 8; nf++) {
        int d0 = nf * 8 + (lane & 3) * 2;
        *reinterpret_cast<half2*>(atth + (size_t)r0 * Ii + hcol + d0) =
            __floats2half2_rn(O[nf][0] * inv0, O[nf][1] * inv0);
        *reinterpret_cast<half2*>(atth + (size_t)r1 * Ii + hcol + d0) =
            __floats2half2_rn(O[nf][2] * inv1, O[nf][3] * inv1);
    }
}

// ---------------------------------------------------------------------------
// LayerNorm -> fp16
// ---------------------------------------------------------------------------
__global__ __launch_bounds__(256) void ln_kernel(
    const float* __restrict__ x, const float* __restrict__ g, const float* __restrict__ b,
    half* __restrict__ oh)
{
    size_t row = blockIdx.x;
    const float* xr = x + row * Dm;
    __shared__ float red[256];
    int t = threadIdx.x;
    float v[4];
    float s = 0.f;
    #pragma unroll
    for (int j = 0; j < 4; j++) { v[j] = xr[t + j * 256]; s += v[j]; }
    red[t] = s; __syncthreads();
    for (int o = 128; o > 0; o >>= 1) { if (t < o) red[t] += red[t + o]; __syncthreads(); }
    float mean = red[0] * (1.f / Dm);
    __syncthreads();
    float s2 = 0.f;
    #pragma unroll
    for (int j = 0; j < 4; j++) { float d = v[j] - mean; s2 += d * d; }
    red[t] = s2; __syncthreads();
    for (int o = 128; o > 0; o >>= 1) { if (t < o) red[t] += red[t + o]; __syncthreads(); }
    float inv = rsqrtf(red[0] * (1.f / Dm) + 1e-5f);
    #pragma unroll
    for (int j = 0; j < 4; j++) {
        int i = t + j * 256;
        oh[row * Dm + i] = __float2half_rn((v[j] - mean) * inv * g[i] + b[i]);
    }
}

// ---------------------------------------------------------------------------
// Softmax -> split fp16 (cross-attn)
// ---------------------------------------------------------------------------
__global__ __launch_bounds__(256) void softmax_split_kernel(
    const float* __restrict__ s, half* __restrict__ ph, half* __restrict__ pl,
    int cols, int ldin, int ldout)
{
    size_t row = blockIdx.x;
    const float* r = s + row * (size_t)ldin;
    __shared__ float red[256];
    int t = threadIdx.x;
    float v = (t < cols) ? r[t] : -INFINITY;
    red[t] = v; __syncthreads();
    for (int o = 128; o > 0; o >>= 1) { if (t < o) red[t] = fmaxf(red[t], red[t + o]); __syncthreads(); }
    float m = red[0]; __syncthreads();
    float e = (t < cols) ? __expf(v - m) : 0.f;
    red[t] = e; __syncthreads();
    for (int o = 128; o > 0; o >>= 1) { if (t < o) red[t] += red[t + o]; __syncthreads(); }
    float inv = 1.f / red[0];
    if (t < ldout) {
        half h, l; split2(e * inv, h, l);
        ph[row * (size_t)ldout + t] = h;
        pl[row * (size_t)ldout + t] = l;
    }
}

// ---------------------------------------------------------------------------
// Plain fp32 -> fp16
// ---------------------------------------------------------------------------
__global__ __launch_bounds__(256) void tohalf_kernel(
    const float* __restrict__ src, half* __restrict__ dh, long long n)
{
    long long i = (long long)blockIdx.x * 256 + threadIdx.x;
    if (i >= n) return;
    dh[i] = __float2half_rn(src[i]);
}

// ---------------------------------------------------------------------------
// Transpose: src [R x C] fp32 -> dst [C x R] fp16
// ---------------------------------------------------------------------------
__global__ __launch_bounds__(1024) void thalf_kernel(
    const float* __restrict__ src, half* __restrict__ dh, int R, int C)
{
    __shared__ float tile[32][33];
    int c0 = blockIdx.x * 32, r0 = blockIdx.y * 32;
    int tx = threadIdx.x, ty = threadIdx.y;
    int r = r0 + ty, c = c0 + tx;
    tile[ty][tx] = (r < R && c < C) ? src[(size_t)r * C + c] : 0.f;
    __syncthreads();
    int rr = r0 + tx, cc = c0 + ty;
    if (rr < R && cc < C)
        dh[(size_t)cc * R + rr] = __float2half_rn(tile[tx][ty]);
}

// ---------------------------------------------------------------------------
// Interleaved transpose for Wff1: src [R x 2FF] -> dst row (2j or 2j+1) x R
//   out row = (cc < FFd) ? 2*cc : 2*(cc-FFd)+1
// ---------------------------------------------------------------------------
__global__ __launch_bounds__(1024) void thalf_ff1_kernel(
    const float* __restrict__ src, half* __restrict__ dh, int R, int C)
{
    __shared__ float tile[32][33];
    int c0 = blockIdx.x * 32, r0 = blockIdx.y * 32;
    int tx = threadIdx.x, ty = threadIdx.y;
    int r = r0 + ty, c = c0 + tx;
    tile[ty][tx] = (r < R && c < C) ? src[(size_t)r * C + c] : 0.f;
    __syncthreads();
    int rr = r0 + tx, cc = c0 + ty;
    if (rr < R && cc < C) {
        int outrow = (cc < FFd) ? 2 * cc : 2 * (cc - FFd) + 1;
        dh[(size_t)outrow * R + rr] = __float2half_rn(tile[tx][ty]);
    }
}

// ---------------------------------------------------------------------------
// Per-head transpose of V
// ---------------------------------------------------------------------------
__global__ __launch_bounds__(1024) void head_t_kernel(
    const float* __restrict__ src, half* __restrict__ dh,
    int T, int Tpad)
{
    __shared__ float tile[32][33];
    int zh = blockIdx.z;
    int b = zh >> 4, h = zh & 15;
    int tx = threadIdx.x, ty = threadIdx.y;
    int t0 = blockIdx.x * 32, d0 = blockIdx.y * 32;
    int t = t0 + ty, d = d0 + tx;
    tile[ty][tx] = (t < T) ? src[((size_t)b * T + t) * 1024 + h * 64 + d] : 0.f;
    __syncthreads();
    int dd = d0 + ty, tt = t0 + tx;
    if (tt < Tpad) {
        size_t base = (size_t)zh * 64 * Tpad + (size_t)dd * Tpad + tt;
        dh[base] = __float2half_rn(tile[tx][ty]);
    }
}

// ---------------------------------------------------------------------------
// Orchestration
// ---------------------------------------------------------------------------
static inline dim3 ggrid(int M, int N, int z) { return dim3((N + 127) / 128, (M + 127) / 128, z); }

#define SYM(p, s) cudaGetSymbolAddress((void**)&p, s)

extern "C" void kernel_launch(void* const* d_in, const int* in_sizes, int n_in,
                              void* d_out, int out_size)
{
    const float* x     = (const float*)d_in[0];
    const float* ctx   = (const float*)d_in[1];
    const float* ln1_g = (const float*)d_in[2];
    const float* ln1_b = (const float*)d_in[3];
    const float* ln2_g = (const float*)d_in[4];
    const float* ln2_b = (const float*)d_in[5];
    const float* ln3_g = (const float*)d_in[6];
    const float* ln3_b = (const float*)d_in[7];
    const float* Wq1   = (const float*)d_in[8];
    const float* Wk1   = (const float*)d_in[9];
    const float* Wv1   = (const float*)d_in[10];
    const float* Wo1   = (const float*)d_in[11];
    const float* bo1   = (const float*)d_in[12];
    const float* Wq2   = (const float*)d_in[13];
    const float* Wk2   = (const float*)d_in[14];
    const float* Wv2   = (const float*)d_in[15];
    const float* Wo2   = (const float*)d_in[16];
    const float* bo2   = (const float*)d_in[17];
    const float* Wff1  = (const float*)d_in[18];
    const float* bff1  = (const float*)d_in[19];
    const float* Wff2  = (const float*)d_in[20];
    const float* bff2  = (const float*)d_in[21];
    float* out = (float*)d_out;

    half *lnh,*qh,*kh,*vth,*Ph,*Pl,*atth,*ctxh,*ffh;
    half *wq1h,*wk1h,*wv1h,*wo1h,*wq2h,*wk2h,*wv2h,*wo2h,*wf1h,*wf2h;
    float *v,*sim,*x1,*x2;
    SYM(lnh,g_lnh); SYM(qh,g_qh); SYM(kh,g_kh);
    SYM(v,g_v); SYM(vth,g_vth); SYM(sim,g_sim); SYM(Ph,g_Ph); SYM(Pl,g_Pl);
    SYM(atth,g_atth); SYM(x1,g_x1); SYM(x2,g_x2);
    SYM(ctxh,g_ctxh); SYM(ffh,g_ffh);
    SYM(wq1h,g_wq1h); SYM(wk1h,g_wk1h); SYM(wv1h,g_wv1h); SYM(wo1h,g_wo1h);
    SYM(wq2h,g_wq2h); SYM(wk2h,g_wk2h); SYM(wv2h,g_wv2h); SYM(wo2h,g_wo2h);
    SYM(wf1h,g_wf1h); SYM(wf2h,g_wf2h);

    cudaFuncSetAttribute((const void*)mma_gemm<0,0>, cudaFuncAttributeMaxDynamicSharedMemorySize, SMEM_G1);
    cudaFuncSetAttribute((const void*)mma_gemm<1,0>, cudaFuncAttributeMaxDynamicSharedMemorySize, SMEM_G2);
    cudaFuncSetAttribute((const void*)mma_gemm<0,1>, cudaFuncAttributeMaxDynamicSharedMemorySize, SMEM_G1);
    cudaFuncSetAttribute((const void*)flash_attn, cudaFuncAttributeMaxDynamicSharedMemorySize, FA_SMEM_BYTES);

    dim3 tb(32, 32);
    // ---- weight transposes ----
    thalf_kernel<<<dim3(Ii/32, Dm/32), tb>>>(Wq1, wq1h, Dm, Ii);
    thalf_kernel<<<dim3(Ii/32, Dm/32), tb>>>(Wk1, wk1h, Dm, Ii);
    thalf_kernel<<<dim3(Ii/32, Dm/32), tb>>>(Wv1, wv1h, Dm, Ii);
    thalf_kernel<<<dim3(Dm/32, Ii/32), tb>>>(Wo1, wo1h, Ii, Dm);
    thalf_kernel<<<dim3(Ii/32, Dm/32), tb>>>(Wq2, wq2h, Dm, Ii);
    thalf_kernel<<<dim3(Ii/32, DCc/32), tb>>>(Wk2, wk2h, DCc, Ii);
    thalf_kernel<<<dim3(Ii/32, DCc/32), tb>>>(Wv2, wv2h, DCc, Ii);
    thalf_kernel<<<dim3(Dm/32, Ii/32), tb>>>(Wo2, wo2h, Ii, Dm);
    thalf_ff1_kernel<<<dim3((2*FFd)/32, Dm/32), tb>>>(Wff1, wf1h, Dm, 2*FFd);
    thalf_kernel<<<dim3(Dm/32, FFd/32), tb>>>(Wff2, wf2h, FFd, Dm);
    tohalf_kernel<<<(BM2*DCc + 255)/256, 256>>>(ctx, ctxh, (long long)BM2*DCc);

    // ================= block 1: self-attention =================
    ln_kernel<<<BN, 256>>>(x, ln1_g, ln1_b, lnh);

    mma_gemm<0,0><<<ggrid(BN, Ii, 1), 256, SMEM_G1>>>(lnh, nullptr, wq1h, nullptr, nullptr,
        nullptr, qh, BN, Ii, Dm, Dm, Dm, Ii, 0,0,0,0,0,0, 1, SCALE);
    mma_gemm<0,0><<<ggrid(BN, Ii, 1), 256, SMEM_G1>>>(lnh, nullptr, wk1h, nullptr, nullptr,
        nullptr, kh, BN, Ii, Dm, Dm, Dm, Ii, 0,0,0,0,0,0, 1, 1.f);
    mma_gemm<0,0><<<ggrid(BN, Ii, 1), 256, SMEM_G1>>>(lnh, nullptr, wv1h, nullptr, nullptr,
        v, nullptr, BN, Ii, Dm, Dm, Dm, Ii, 0,0,0,0,0,0, 1, 1.f);

    head_t_kernel<<<dim3(Ntok/32, 2, BHh), tb>>>(v, vth, Ntok, Ntok);

    flash_attn<<<dim3(Ntok/128, BHh), 256, FA_SMEM_BYTES>>>(qh, kh, vth, atth);

    // x1 = att @ Wo1 + bo1 + x
    mma_gemm<0,0><<<ggrid(BN, Dm, 1), 256, SMEM_G1>>>(atth, nullptr, wo1h, bo1, x,
        x1, nullptr, BN, Dm, Ii, Ii, Ii, Dm, 0,0,0,0,0,0, 1, 1.f);

    // ================= block 2: cross-attention =================
    ln_kernel<<<BN, 256>>>(x1, ln2_g, ln2_b, lnh);

    mma_gemm<0,0><<<ggrid(BN, Ii, 1), 256, SMEM_G1>>>(lnh, nullptr, wq2h, nullptr, nullptr,
        nullptr, qh, BN, Ii, Dm, Dm, Dm, Ii, 0,0,0,0,0,0, 1, SCALE);
    mma_gemm<0,0><<<ggrid(BM2, Ii, 1), 256, SMEM_G1>>>(ctxh, nullptr, wk2h, nullptr, nullptr,
        nullptr, kh, BM2, Ii, DCc, DCc, DCc, Ii, 0,0,0,0,0,0, 1, 1.f);
    mma_gemm<0,0><<<ggrid(BM2, Ii, 1), 256, SMEM_G1>>>(ctxh, nullptr, wv2h, nullptr, nullptr,
        v, nullptr, BM2, Ii, DCc, DCc, DCc, Ii, 0,0,0,0,0,0, 1, 1.f);

    head_t_kernel<<<dim3((MctxP+31)/32, 2, BHh), tb>>>(v, vth, Mctx, MctxP);

    mma_gemm<0,0><<<ggrid(Ntok, Mctx, BHh), 256, SMEM_G1>>>(qh, nullptr, kh, nullptr, nullptr,
        sim, nullptr, Ntok, Mctx, DHd, Ii, Ii, MctxP,
        (long long)Ntok*Ii, 64, (long long)Mctx*Ii, 64,
        (long long)Hh*Ntok*MctxP, (long long)Ntok*MctxP, Hh, 1.f);

    softmax_split_kernel<<<BHh*Ntok, 256>>>(sim, Ph, Pl, Mctx, MctxP, MctxP);

    mma_gemm<1,0><<<ggrid(Ntok, DHd, BHh), 256, SMEM_G2>>>(Ph, Pl, vth, nullptr, nullptr,
        nullptr, atth, Ntok, DHd, MctxP, MctxP, MctxP, Ii,
        (long long)Hh*Ntok*MctxP, (long long)Ntok*MctxP,
        (long long)Hh*DHd*MctxP, (long long)DHd*MctxP,
        (long long)Ntok*Ii, 64, Hh, 1.f);

    // x2 = att @ Wo2 + bo2 + x1
    mma_gemm<0,0><<<ggrid(BN, Dm, 1), 256, SMEM_G1>>>(atth, nullptr, wo2h, bo2, x1,
        x2, nullptr, BN, Dm, Ii, Ii, Ii, Dm, 0,0,0,0,0,0, 1, 1.f);

    // ================= block 3: GEGLU FF (fused epilogue) =================
    ln_kernel<<<BN, 256>>>(x2, ln3_g, ln3_b, lnh);

    // FF1 with interleaved (h,gate) cols -> ffh = h * gelu(gate), ld = FFd
    mma_gemm<0,1><<<ggrid(BN, 2*FFd, 1), 256, SMEM_G1>>>(lnh, nullptr, wf1h, bff1, nullptr,
        nullptr, ffh, BN, 2*FFd, Dm, Dm, Dm, FFd, 0,0,0,0,0,0, 1, 1.f);

    mma_gemm<0,0><<<ggrid(BN, Dm, 1), 256, SMEM_G1>>>(ffh, nullptr, wf2h, bff2, x2,
        out, nullptr, BN, Dm, FFd, FFd, FFd, Dm, 0,0,0,0,0,0, 1, 1.f);
}